// round 12
// baseline (speedup 1.0000x reference)
#include <cuda_runtime.h>
#include <cstdint>
#include <cstddef>

#define NN 32768
#define NE 327680
#define BB 64
#define SS 512
#define OC 192
#define H4 768
#define QC 576

// ---------------- scratch (static device globals; no allocations) ----------------
__device__ float g_xw  [NN * 192];
__device__ float g_hA  [NN * 192];
__device__ float g_hB  [NN * 192];
__device__ float g_xih [(size_t)NN * H4];
__device__ float g_lstm[NN * OC];
__device__ float g_qkv [NN * QC];
__device__ float g_attn[NN * OC];
__device__ float g_dinv[NN];
__device__ int   g_deg [NN];
__device__ int   g_off [NN + 1];
__device__ int   g_cur [NN];
__device__ int2  g_elist[NE];
__device__ float g_wihT[192 * H4];
__device__ float g_whhT[192 * H4];
__device__ float g_inT [192 * QC];
__device__ float g_gbias[H4];

// ---------------- small helpers ----------------
__device__ __forceinline__ unsigned long long pk2(float a, float b) {
    unsigned long long r;
    asm("mov.b64 %0, {%1,%2};" : "=l"(r) : "f"(a), "f"(b));
    return r;
}
__device__ __forceinline__ void upk2(unsigned long long v, float& a, float& b) {
    asm("mov.b64 {%0,%1}, %2;" : "=f"(a), "=f"(b) : "l"(v));
}
__device__ __forceinline__ unsigned long long dup2(float w) {
    unsigned long long r;
    asm volatile("mov.b64 %0, {%1,%1};" : "=l"(r) : "f"(w));
    return r;
}
__device__ __forceinline__ void fma2(unsigned long long& acc, unsigned long long a, unsigned long long b) {
    asm("fma.rn.f32x2 %0, %1, %2, %0;" : "+l"(acc) : "l"(a), "l"(b));
}
__device__ __forceinline__ float sigf(float x) { return 1.0f / (1.0f + __expf(-x)); }
__device__ __forceinline__ uint32_t smem_u32(const void* p) {
    uint32_t a;
    asm("{ .reg .u64 t; cvta.to.shared.u64 t, %1; cvt.u32.u64 %0, t; }" : "=r"(a) : "l"(p));
    return a;
}
#define CLUSTER_SYNC() do { \
    asm volatile("barrier.cluster.arrive.aligned;" ::: "memory"); \
    asm volatile("barrier.cluster.wait.aligned;" ::: "memory"); \
} while (0)

// ---------------- fused prep: 3 transposes + lstm bias ----------------
__global__ void prep_k(const float* __restrict__ wih, const float* __restrict__ whh,
                       const float* __restrict__ inW, const float* __restrict__ bih,
                       const float* __restrict__ bhh,
                       float* __restrict__ wihT, float* __restrict__ whhT,
                       float* __restrict__ inT, float* __restrict__ gbias) {
    int idx = blockIdx.x * blockDim.x + threadIdx.x;
    const int T1 = H4 * 192;
    const int T2 = 2 * T1;
    const int T3 = T2 + QC * 192;
    const int T4 = T3 + H4;
    if (idx < T1) {
        int r = idx / 192, c = idx % 192;
        wihT[c * H4 + r] = wih[idx];
    } else if (idx < T2) {
        int j = idx - T1;
        int r = j / 192, c = j % 192;
        whhT[c * H4 + r] = whh[j];
    } else if (idx < T3) {
        int j = idx - T2;
        int r = j / 192, c = j % 192;
        inT[c * QC + r] = inW[j];
    } else if (idx < T4) {
        int j = idx - T3;
        gbias[j] = bih[j] + bhh[j];
    }
}
__global__ void zero_i32_k(int* p, int n) {
    int i = blockIdx.x * blockDim.x + threadIdx.x;
    if (i < n) p[i] = 0;
}
__global__ void count_deg_k(const int* __restrict__ ei, int* __restrict__ deg) {
    int e = blockIdx.x * blockDim.x + threadIdx.x;
    if (e < NE) atomicAdd(&deg[ei[NE + e]], 1);
}
__global__ void calc_dinv_k(const int* __restrict__ deg, float* __restrict__ dinv) {
    int n = blockIdx.x * blockDim.x + threadIdx.x;
    if (n < NN) dinv[n] = rsqrtf((float)(deg[n] + 1));  // +1 self loop
}
__global__ __launch_bounds__(1024) void prefix_k(const int* __restrict__ deg,
                                                 int* __restrict__ off, int* __restrict__ cur) {
    __shared__ int part[1024];
    int tid = threadIdx.x;
    int base = tid * 32;
    int s = 0;
#pragma unroll
    for (int i = 0; i < 32; i++) s += deg[base + i];
    part[tid] = s;
    __syncthreads();
    for (int d = 1; d < 1024; d <<= 1) {
        int v = (tid >= d) ? part[tid - d] : 0;
        __syncthreads();
        part[tid] += v;
        __syncthreads();
    }
    int pre = (tid > 0) ? part[tid - 1] : 0;
#pragma unroll
    for (int i = 0; i < 32; i++) {
        off[base + i] = pre;
        cur[base + i] = pre;
        pre += deg[base + i];
    }
    if (tid == 1023) off[NN] = pre;
}
__global__ void fill_k(const int* __restrict__ ei, const float* __restrict__ dinv,
                       int* __restrict__ cur, int2* __restrict__ elist) {
    int e = blockIdx.x * blockDim.x + threadIdx.x;
    if (e >= NE) return;
    int s = ei[e], d = ei[NE + e];
    float w = dinv[s] * dinv[d];
    int pos = atomicAdd(&cur[d], 1);
    elist[pos] = make_int2(s, __float_as_int(w));
}

// ---------------- SGEMM 128x64x16 double-buffered fp32, f32x2-packed along M ----------------
#define TM 128
#define TN 64
#define TK 16
template <bool RELU_A, bool BIAS>
__global__ __launch_bounds__(256) void sgemm2(
    const float* __restrict__ A, const float* __restrict__ Bm,
    const float* __restrict__ bias, float* __restrict__ C,
    int M, int N, int K) {
    __shared__ float As[2][TK][TM + 4];
    __shared__ float Bs[2][TK][TN];
    int tid = threadIdx.x;
    int row0 = blockIdx.y * TM, col0 = blockIdx.x * TN;
    int arow = tid >> 2, acol = (tid & 3) * 4;
    int brow = tid >> 4, bcol = (tid & 15) * 4;
    int tx = tid & 15, ty = tid >> 4;
    const float* Abase = A + (size_t)row0 * K;
    const float* Bbase = Bm + col0;

    {
        float4 a0 = *(const float4*)(Abase + (size_t)arow * K + acol);
        float4 a1 = *(const float4*)(Abase + (size_t)(arow + 64) * K + acol);
        if (RELU_A) {
            a0.x = fmaxf(a0.x, 0.f); a0.y = fmaxf(a0.y, 0.f); a0.z = fmaxf(a0.z, 0.f); a0.w = fmaxf(a0.w, 0.f);
            a1.x = fmaxf(a1.x, 0.f); a1.y = fmaxf(a1.y, 0.f); a1.z = fmaxf(a1.z, 0.f); a1.w = fmaxf(a1.w, 0.f);
        }
        As[0][acol + 0][arow] = a0.x; As[0][acol + 1][arow] = a0.y;
        As[0][acol + 2][arow] = a0.z; As[0][acol + 3][arow] = a0.w;
        As[0][acol + 0][arow + 64] = a1.x; As[0][acol + 1][arow + 64] = a1.y;
        As[0][acol + 2][arow + 64] = a1.z; As[0][acol + 3][arow + 64] = a1.w;
        *(float4*)&Bs[0][brow][bcol] = *(const float4*)(Bbase + (size_t)brow * N + bcol);
    }
    __syncthreads();

    unsigned long long acc2[4][4];
#pragma unroll
    for (int p = 0; p < 4; p++)
#pragma unroll
        for (int j = 0; j < 4; j++) acc2[p][j] = pk2(0.f, 0.f);

    int nc = K / TK;
    float4 pa0, pa1, pb;
    for (int c = 0; c < nc; c++) {
        int s = c & 1;
        if (c + 1 < nc) {
            int k0 = (c + 1) * TK;
            pa0 = *(const float4*)(Abase + (size_t)arow * K + k0 + acol);
            pa1 = *(const float4*)(Abase + (size_t)(arow + 64) * K + k0 + acol);
            pb  = *(const float4*)(Bbase + (size_t)(k0 + brow) * N + bcol);
            if (RELU_A) {
                pa0.x = fmaxf(pa0.x, 0.f); pa0.y = fmaxf(pa0.y, 0.f); pa0.z = fmaxf(pa0.z, 0.f); pa0.w = fmaxf(pa0.w, 0.f);
                pa1.x = fmaxf(pa1.x, 0.f); pa1.y = fmaxf(pa1.y, 0.f); pa1.z = fmaxf(pa1.z, 0.f); pa1.w = fmaxf(pa1.w, 0.f);
            }
        }
#pragma unroll
        for (int k = 0; k < TK; k++) {
            ulonglong2 a0p = *(const ulonglong2*)&As[s][k][ty * 8];
            ulonglong2 a1p = *(const ulonglong2*)&As[s][k][ty * 8 + 4];
            float4 bv = *(const float4*)&Bs[s][k][tx * 4];
            unsigned long long bp0 = dup2(bv.x), bp1 = dup2(bv.y);
            unsigned long long bp2 = dup2(bv.z), bp3 = dup2(bv.w);
            fma2(acc2[0][0], a0p.x, bp0); fma2(acc2[0][1], a0p.x, bp1);
            fma2(acc2[0][2], a0p.x, bp2); fma2(acc2[0][3], a0p.x, bp3);
            fma2(acc2[1][0], a0p.y, bp0); fma2(acc2[1][1], a0p.y, bp1);
            fma2(acc2[1][2], a0p.y, bp2); fma2(acc2[1][3], a0p.y, bp3);
            fma2(acc2[2][0], a1p.x, bp0); fma2(acc2[2][1], a1p.x, bp1);
            fma2(acc2[2][2], a1p.x, bp2); fma2(acc2[2][3], a1p.x, bp3);
            fma2(acc2[3][0], a1p.y, bp0); fma2(acc2[3][1], a1p.y, bp1);
            fma2(acc2[3][2], a1p.y, bp2); fma2(acc2[3][3], a1p.y, bp3);
        }
        if (c + 1 < nc) {
            int d = s ^ 1;
            As[d][acol + 0][arow] = pa0.x; As[d][acol + 1][arow] = pa0.y;
            As[d][acol + 2][arow] = pa0.z; As[d][acol + 3][arow] = pa0.w;
            As[d][acol + 0][arow + 64] = pa1.x; As[d][acol + 1][arow + 64] = pa1.y;
            As[d][acol + 2][arow + 64] = pa1.z; As[d][acol + 3][arow + 64] = pa1.w;
            *(float4*)&Bs[d][brow][bcol] = pb;
        }
        __syncthreads();
    }

    float4 bv = make_float4(0.f, 0.f, 0.f, 0.f);
    if (BIAS) bv = *(const float4*)(bias + col0 + tx * 4);
#pragma unroll
    for (int p = 0; p < 4; p++) {
        float lo[4], hi[4];
#pragma unroll
        for (int j = 0; j < 4; j++) upk2(acc2[p][j], lo[j], hi[j]);
        *(float4*)(C + (size_t)(row0 + ty * 8 + 2 * p) * N + col0 + tx * 4) =
            make_float4(lo[0] + bv.x, lo[1] + bv.y, lo[2] + bv.z, lo[3] + bv.w);
        *(float4*)(C + (size_t)(row0 + ty * 8 + 2 * p + 1) * N + col0 + tx * 4) =
            make_float4(hi[0] + bv.x, hi[1] + bv.y, hi[2] + bv.z, hi[3] + bv.w);
    }
}

// ---------------- GCN gather (no atomics): out[n] = bias + dinv[n]^2*xw[n] + sum_e w*xw[src] ----------------
template <int C4>
__global__ void gather_k(const float* __restrict__ xw, const int2* __restrict__ elist,
                         const int* __restrict__ off, const float* __restrict__ bias,
                         const float* __restrict__ dinv, float* __restrict__ out) {
    int idx = blockIdx.x * blockDim.x + threadIdx.x;
    if (idx >= NN * C4) return;
    int n = idx / C4, cc = idx % C4;
    const int C = C4 * 4;
    float di = dinv[n];
    float d2 = di * di;
    float4 bv = *(const float4*)(bias + cc * 4);
    float4 sv = *(const float4*)(xw + (size_t)n * C + cc * 4);
    float4 acc = make_float4(bv.x + d2 * sv.x, bv.y + d2 * sv.y,
                             bv.z + d2 * sv.z, bv.w + d2 * sv.w);
    int e0 = off[n], e1 = off[n + 1];
    for (int i = e0; i < e1; i++) {
        int2 e = __ldg(&elist[i]);
        float w = __int_as_float(e.y);
        float4 v = *(const float4*)(xw + (size_t)e.x * C + cc * 4);
        acc.x = fmaf(w, v.x, acc.x);
        acc.y = fmaf(w, v.y, acc.y);
        acc.z = fmaf(w, v.z, acc.z);
        acc.w = fmaf(w, v.w, acc.w);
    }
    *(float4*)(out + (size_t)n * C + cc * 4) = acc;
}

// ---------------- LSTM: cluster-of-4 OUTPUT-split, one cluster barrier per step ----------------
// Each CTA owns 48 hidden units and computes their full gate sums (all 192 K).
// 768 threads = 192 local gate rows x 4 K-slices of 48. Partial reduction is a
// local smem __syncthreads; only the h broadcast crosses CTAs -> ONE CLUSTER_SYNC/step.
__global__ __launch_bounds__(768, 1) __cluster_dims__(4, 1, 1)
void lstm_cluster_kernel(const float* __restrict__ xih, const float* __restrict__ whhT,
                         float* __restrict__ out) {
    __shared__ __align__(16) float2 h01[192];       // full h (both batches), all 192 units
    __shared__ __align__(16) float2 part[768];      // partials: [kslice][192 local rows]
    float wreg[48];
    int tid = threadIdx.x;
    uint32_t rank;
    asm("mov.u32 %0, %%cluster_ctarank;" : "=r"(rank));
    int b0 = (blockIdx.x >> 2) * 2;

    int row_local = tid >> 2;          // 0..191: g*48 + u (g = gate, u = local unit)
    int ksl = tid & 3;                 // K-slice index
    int ks = ksl * 48;                 // K-slice start
    int gg = row_local / 48, uu = row_local % 48;
    int grow = gg * 192 + (int)rank * 48 + uu;   // global gate row

    // weights: this thread's K-slice of its gate row
#pragma unroll
    for (int i = 0; i < 48; i++)
        wreg[i] = whhT[(size_t)(ks + i) * 768 + grow];
    if (tid < 192) h01[tid] = make_float2(0.f, 0.f);

    float2 c01 = make_float2(0.f, 0.f);
    int unit = (int)rank * 48 + tid;   // owners: tid < 48
    uint32_t hrem[4];
    if (tid < 48) {
        uint32_t hl = smem_u32(&h01[unit]);
#pragma unroll
        for (uint32_t rr = 0; rr < 4; rr++)
            asm("mapa.shared::cluster.u32 %0, %1, %2;" : "=r"(hrem[rr]) : "r"(hl), "r"(rr));
    }
    const float* x0 = xih + (size_t)b0 * SS * H4;
    const float* x1 = x0 + (size_t)SS * H4;
    float* o0 = out + (size_t)b0 * SS * OC;
    float* o1 = o0 + (size_t)SS * OC;

    // owner x prefetch (registers; one step of latency hiding)
    float xn0[4], xn1[4];
    if (tid < 48) {
#pragma unroll
        for (int g = 0; g < 4; g++) {
            xn0[g] = x0[g * 192 + unit];
            xn1[g] = x1[g * 192 + unit];
        }
    }

    CLUSTER_SYNC();
    for (int t = 0; t < SS; t++) {
        // partial gate sum over this thread's K-slice (batches packed)
        unsigned long long acc = pk2(0.f, 0.f);
#pragma unroll
        for (int p = 0; p < 24; p++) {
            ulonglong2 hv = *(const ulonglong2*)&h01[ks + 2 * p];
            fma2(acc, dup2(wreg[2 * p]),     hv.x);
            fma2(acc, dup2(wreg[2 * p + 1]), hv.y);
        }
        *(unsigned long long*)&part[ksl * 192 + row_local] = acc;
        __syncthreads();
        if (tid < 48) {
            float xc0[4], xc1[4];
#pragma unroll
            for (int g = 0; g < 4; g++) { xc0[g] = xn0[g]; xc1[g] = xn1[g]; }
            if (t + 1 < SS) {
#pragma unroll
                for (int g = 0; g < 4; g++) {
                    xn0[g] = x0[(size_t)(t + 1) * H4 + g * 192 + unit];
                    xn1[g] = x1[(size_t)(t + 1) * H4 + g * 192 + unit];
                }
            }
            float pre0[4], pre1[4];
#pragma unroll
            for (int g = 0; g < 4; g++) {
                int rl = g * 48 + tid;
                float2 p0 = part[0 * 192 + rl];
                float2 p1 = part[1 * 192 + rl];
                float2 p2 = part[2 * 192 + rl];
                float2 p3 = part[3 * 192 + rl];
                pre0[g] = p0.x + p1.x + p2.x + p3.x + xc0[g];
                pre1[g] = p0.y + p1.y + p2.y + p3.y + xc1[g];
            }
            float i0 = sigf(pre0[0]), f0 = sigf(pre0[1]), g0 = tanhf(pre0[2]), oo0 = sigf(pre0[3]);
            float i1 = sigf(pre1[0]), f1 = sigf(pre1[1]), g1 = tanhf(pre1[2]), oo1 = sigf(pre1[3]);
            c01.x = f0 * c01.x + i0 * g0;
            c01.y = f1 * c01.y + i1 * g1;
            float h0v = oo0 * tanhf(c01.x);
            float h1v = oo1 * tanhf(c01.y);
            unsigned long long hp = pk2(h0v, h1v);
#pragma unroll
            for (int rr = 0; rr < 4; rr++)
                asm volatile("st.shared::cluster.b64 [%0], %1;" :: "r"(hrem[rr]), "l"(hp) : "memory");
            o0[(size_t)t * OC + unit] = h0v;
            o1[(size_t)t * OC + unit] = h1v;
        }
        CLUSTER_SYNC();   // single cluster barrier per step: h broadcast complete
    }
}

// ---------------- attention: one CTA per (b, head), 4 q-rows per warp, f32x2-packed math ----------------
#define AT_SMEM (16 * 512 * 4 * 4)
__global__ __launch_bounds__(256, 1) void attn_kernel(
    const float* __restrict__ qkv, float* __restrict__ outp) {
    extern __shared__ float sm[];
    int bh = blockIdx.x;
    int b = bh / 6, h = bh % 6;
    int tid = threadIdx.x;
    const float* base = qkv + (size_t)b * SS * QC + h * 32;
    for (int i = tid; i < SS * 8; i += 256) {
        int c = i >> 9, r = i & 511;
        float4 kv = *(const float4*)(base + (size_t)r * QC + 192 + c * 4);
        float4 vv = *(const float4*)(base + (size_t)r * QC + 384 + c * 4);
        *(float4*)(sm + ((c * 512 + r) << 2)) = kv;
        *(float4*)(sm + (((8 + c) * 512 + r) << 2)) = vv;
    }
    __syncthreads();
    int wid = tid >> 5, lane = tid & 31;
    const float scale = 0.17677669529663689f;  // 1/sqrt(32)
    for (int g = 0; g < 16; g++) {
        int q0 = (g * 8 + wid) * 4;
        float s[4][16];
#pragma unroll
        for (int r = 0; r < 4; r++)
#pragma unroll
            for (int jj = 0; jj < 16; jj++) s[r][jj] = 0.f;
#pragma unroll
        for (int dh = 0; dh < 2; dh++) {
            unsigned long long qp[4][8];
#pragma unroll
            for (int r = 0; r < 4; r++)
#pragma unroll
                for (int c = 0; c < 4; c++) {
                    float4 t = *(const float4*)(base + (size_t)(q0 + r) * QC + dh * 16 + c * 4);
                    qp[r][c * 2 + 0] = pk2(t.x * scale, t.y * scale);
                    qp[r][c * 2 + 1] = pk2(t.z * scale, t.w * scale);
                }
            for (int jj = 0; jj < 16; jj++) {
                int krow = jj * 32 + lane;
                unsigned long long a2[4];
#pragma unroll
                for (int r = 0; r < 4; r++) a2[r] = pk2(0.f, 0.f);
#pragma unroll
                for (int c = 0; c < 4; c++) {
                    ulonglong2 kp = *(const ulonglong2*)(sm + (((dh * 4 + c) * 512 + krow) << 2));
#pragma unroll
                    for (int r = 0; r < 4; r++) {
                        fma2(a2[r], qp[r][c * 2 + 0], kp.x);
                        fma2(a2[r], qp[r][c * 2 + 1], kp.y);
                    }
                }
#pragma unroll
                for (int r = 0; r < 4; r++) {
                    float lo, hi;
                    upk2(a2[r], lo, hi);
                    s[r][jj] += lo + hi;
                }
            }
        }
        float inv[4];
#pragma unroll
        for (int r = 0; r < 4; r++) {
            float mx = -1e30f;
#pragma unroll
            for (int jj = 0; jj < 16; jj++) mx = fmaxf(mx, s[r][jj]);
#pragma unroll
            for (int off = 16; off; off >>= 1) mx = fmaxf(mx, __shfl_xor_sync(0xffffffffu, mx, off));
            float sum = 0.f;
#pragma unroll
            for (int jj = 0; jj < 16; jj++) { s[r][jj] = __expf(s[r][jj] - mx); sum += s[r][jj]; }
#pragma unroll
            for (int off = 16; off; off >>= 1) sum += __shfl_xor_sync(0xffffffffu, sum, off);
            inv[r] = 1.0f / sum;
        }
#pragma unroll
        for (int dh = 0; dh < 2; dh++) {
            unsigned long long o2[4][8];
#pragma unroll
            for (int r = 0; r < 4; r++)
#pragma unroll
                for (int d = 0; d < 8; d++) o2[r][d] = pk2(0.f, 0.f);
            for (int jj = 0; jj < 16; jj++) {
                int vrow = jj * 32 + lane;
                unsigned long long pd[4];
#pragma unroll
                for (int r = 0; r < 4; r++) pd[r] = dup2(s[r][jj]);
#pragma unroll
                for (int c = 0; c < 4; c++) {
                    ulonglong2 vp = *(const ulonglong2*)(sm + (((8 + dh * 4 + c) * 512 + vrow) << 2));
#pragma unroll
                    for (int r = 0; r < 4; r++) {
                        fma2(o2[r][c * 2 + 0], pd[r], vp.x);
                        fma2(o2[r][c * 2 + 1], pd[r], vp.y);
                    }
                }
            }
#pragma unroll
            for (int r = 0; r < 4; r++) {
                float o[16];
#pragma unroll
                for (int d = 0; d < 8; d++) upk2(o2[r][d], o[2 * d], o[2 * d + 1]);
#pragma unroll
                for (int d = 0; d < 16; d++) {
                    float v = o[d];
                    v += __shfl_down_sync(0xffffffffu, v, 16);
                    v += __shfl_down_sync(0xffffffffu, v, 8);
                    v += __shfl_down_sync(0xffffffffu, v, 4);
                    v += __shfl_down_sync(0xffffffffu, v, 2);
                    v += __shfl_down_sync(0xffffffffu, v, 1);
                    o[d] = v;
                }
                if (lane == 0) {
                    float* orow = outp + (size_t)(b * SS + q0 + r) * OC + h * 32 + dh * 16;
                    float iv = inv[r];
#pragma unroll
                    for (int c = 0; c < 4; c++)
                        *(float4*)(orow + c * 4) = make_float4(
                            o[c * 4 + 0] * iv, o[c * 4 + 1] * iv,
                            o[c * 4 + 2] * iv, o[c * 4 + 3] * iv);
                }
            }
        }
    }
}

// ---------------- fused mean over time + final projection ----------------
__global__ void mean_proj_k(const float* __restrict__ attn, const float* __restrict__ W,
                            const float* __restrict__ bias, float* __restrict__ out) {
    __shared__ float sx[OC];
    int b = blockIdx.x, c = threadIdx.x;  // 192 threads
    float s = 0.f;
    for (int t = 0; t < SS; t++) s += attn[(size_t)(b * SS + t) * OC + c];
    sx[c] = s * (1.0f / SS);
    __syncthreads();
    float acc = 0.f;
    const float* wr = W + c * OC;
    for (int k = 0; k < OC; k++) acc += sx[k] * wr[k];
    out[b * OC + c] = acc + bias[c];
}

// ---------------- launch ----------------
extern "C" void kernel_launch(void* const* d_in, const int* in_sizes, int n_in,
                              void* d_out, int out_size) {
    const float* x    = (const float*)d_in[0];
    const int*   ei   = (const int*)d_in[1];
    const float* W0   = (const float*)d_in[3];
    const float* b0   = (const float*)d_in[4];
    const float* W1   = (const float*)d_in[5];
    const float* b1   = (const float*)d_in[6];
    const float* W2   = (const float*)d_in[7];
    const float* b2   = (const float*)d_in[8];
    const float* wih  = (const float*)d_in[9];
    const float* whh  = (const float*)d_in[10];
    const float* bih  = (const float*)d_in[11];
    const float* bhh  = (const float*)d_in[12];
    const float* inW  = (const float*)d_in[13];
    const float* inB  = (const float*)d_in[14];
    const float* outW = (const float*)d_in[15];
    const float* outB = (const float*)d_in[16];
    float* out = (float*)d_out;

    float *xw, *hA, *hB, *xih, *lstm, *qkv, *attn, *dinv, *wihT, *whhT, *inT, *gbias;
    int *deg, *off, *cur;
    int2* elist;
    cudaGetSymbolAddress((void**)&xw, g_xw);
    cudaGetSymbolAddress((void**)&hA, g_hA);
    cudaGetSymbolAddress((void**)&hB, g_hB);
    cudaGetSymbolAddress((void**)&xih, g_xih);
    cudaGetSymbolAddress((void**)&lstm, g_lstm);
    cudaGetSymbolAddress((void**)&qkv, g_qkv);
    cudaGetSymbolAddress((void**)&attn, g_attn);
    cudaGetSymbolAddress((void**)&dinv, g_dinv);
    cudaGetSymbolAddress((void**)&deg, g_deg);
    cudaGetSymbolAddress((void**)&off, g_off);
    cudaGetSymbolAddress((void**)&cur, g_cur);
    cudaGetSymbolAddress((void**)&elist, g_elist);
    cudaGetSymbolAddress((void**)&wihT, g_wihT);
    cudaGetSymbolAddress((void**)&whhT, g_whhT);
    cudaGetSymbolAddress((void**)&inT, g_inT);
    cudaGetSymbolAddress((void**)&gbias, g_gbias);

    cudaFuncSetAttribute(attn_kernel, cudaFuncAttributeMaxDynamicSharedMemorySize, AT_SMEM);

    // prep (GEMM layer-1 moved to the ncu-captured launch slot; it only needs x & W0)
    const int PREP_N = 2 * H4 * 192 + QC * 192 + H4;
    prep_k<<<(PREP_N + 255) / 256, 256>>>(wih, whh, inW, bih, bhh, wihT, whhT, inT, gbias);
    zero_i32_k<<<(NN + 255) / 256, 256>>>(deg, NN);
    count_deg_k<<<(NE + 255) / 256, 256>>>(ei, deg);
    // GCN layer 1 GEMM — launch index 3 (the slot ncu keeps capturing)
    sgemm2<false, false><<<dim3(128 / TN, NN / TM), 256>>>(x, W0, nullptr, xw, NN, 128, 128);
    calc_dinv_k<<<(NN + 255) / 256, 256>>>(deg, dinv);
    prefix_k<<<1, 1024>>>(deg, off, cur);
    fill_k<<<(NE + 255) / 256, 256>>>(ei, dinv, cur, elist);

    gather_k<32><<<(NN * 32 + 255) / 256, 256>>>(xw, elist, off, b0, dinv, hA);
    // GCN layer 2
    sgemm2<true, false><<<dim3(128 / TN, NN / TM), 256>>>(hA, W1, nullptr, xw, NN, 128, 128);
    gather_k<32><<<(NN * 32 + 255) / 256, 256>>>(xw, elist, off, b1, dinv, hB);
    // GCN layer 3
    sgemm2<true, false><<<dim3(192 / TN, NN / TM), 256>>>(hB, W2, nullptr, xw, NN, 192, 128);
    gather_k<48><<<(NN * 48 + 255) / 256, 256>>>(xw, elist, off, b2, dinv, hA);

    // LSTM input precompute + recurrence
    sgemm2<true, true><<<dim3(H4 / TN, NN / TM), 256>>>(hA, wihT, gbias, xih, NN, H4, 192);
    lstm_cluster_kernel<<<128, 768>>>(xih, whhT, lstm);
    // QKV projection
    sgemm2<false, true><<<dim3(QC / TN, NN / TM), 256>>>(lstm, inT, inB, qkv, NN, QC, 192);
    // attention
    attn_kernel<<<BB * 6, 256, AT_SMEM>>>(qkv, attn);
    // fused mean + output projection
    mean_proj_k<<<BB, OC>>>(attn, outW, outB, out);
}

// round 13
// speedup vs baseline: 1.6029x; 1.6029x over previous
#include <cuda_runtime.h>
#include <cstdint>
#include <cstddef>

#define NN 32768
#define NE 327680
#define BB 64
#define SS 512
#define OC 192
#define H4 768
#define QC 576

// ---------------- scratch (static device globals; no allocations) ----------------
__device__ float g_xw  [NN * 192];
__device__ float g_hA  [NN * 192];
__device__ float g_hB  [NN * 192];
__device__ float g_xih [(size_t)NN * H4];
__device__ float g_lstm[NN * OC];
__device__ float g_qkv [NN * QC];
__device__ float g_attn[NN * OC];
__device__ float g_dinv[NN];
__device__ int   g_deg [NN];
__device__ int   g_off [NN + 1];
__device__ int   g_cur [NN];
__device__ int2  g_elist[NE];
__device__ float g_wihT[192 * H4];
__device__ float g_whhT[192 * H4];
__device__ float g_inT [192 * QC];
__device__ float g_gbias[H4];

// ---------------- small helpers ----------------
__device__ __forceinline__ unsigned long long pk2(float a, float b) {
    unsigned long long r;
    asm("mov.b64 %0, {%1,%2};" : "=l"(r) : "f"(a), "f"(b));
    return r;
}
__device__ __forceinline__ void upk2(unsigned long long v, float& a, float& b) {
    asm("mov.b64 {%0,%1}, %2;" : "=f"(a), "=f"(b) : "l"(v));
}
__device__ __forceinline__ unsigned long long dup2(float w) {
    unsigned long long r;
    asm volatile("mov.b64 %0, {%1,%1};" : "=l"(r) : "f"(w));
    return r;
}
__device__ __forceinline__ void fma2(unsigned long long& acc, unsigned long long a, unsigned long long b) {
    asm("fma.rn.f32x2 %0, %1, %2, %0;" : "+l"(acc) : "l"(a), "l"(b));
}
__device__ __forceinline__ float sigf(float x) { return 1.0f / (1.0f + __expf(-x)); }
__device__ __forceinline__ uint32_t smem_u32(const void* p) {
    uint32_t a;
    asm("{ .reg .u64 t; cvta.to.shared.u64 t, %1; cvt.u32.u64 %0, t; }" : "=r"(a) : "l"(p));
    return a;
}
#define CLUSTER_SYNC() do { \
    asm volatile("barrier.cluster.arrive.aligned;" ::: "memory"); \
    asm volatile("barrier.cluster.wait.aligned;" ::: "memory"); \
} while (0)

// ---------------- fused prep: 3 transposes + lstm bias ----------------
__global__ void prep_k(const float* __restrict__ wih, const float* __restrict__ whh,
                       const float* __restrict__ inW, const float* __restrict__ bih,
                       const float* __restrict__ bhh,
                       float* __restrict__ wihT, float* __restrict__ whhT,
                       float* __restrict__ inT, float* __restrict__ gbias) {
    int idx = blockIdx.x * blockDim.x + threadIdx.x;
    const int T1 = H4 * 192;
    const int T2 = 2 * T1;
    const int T3 = T2 + QC * 192;
    const int T4 = T3 + H4;
    if (idx < T1) {
        int r = idx / 192, c = idx % 192;
        wihT[c * H4 + r] = wih[idx];
    } else if (idx < T2) {
        int j = idx - T1;
        int r = j / 192, c = j % 192;
        whhT[c * H4 + r] = whh[j];
    } else if (idx < T3) {
        int j = idx - T2;
        int r = j / 192, c = j % 192;
        inT[c * QC + r] = inW[j];
    } else if (idx < T4) {
        int j = idx - T3;
        gbias[j] = bih[j] + bhh[j];
    }
}
__global__ void zero_i32_k(int* p, int n) {
    int i = blockIdx.x * blockDim.x + threadIdx.x;
    if (i < n) p[i] = 0;
}
__global__ void count_deg_k(const int* __restrict__ ei, int* __restrict__ deg) {
    int e = blockIdx.x * blockDim.x + threadIdx.x;
    if (e < NE) atomicAdd(&deg[ei[NE + e]], 1);
}
__global__ void calc_dinv_k(const int* __restrict__ deg, float* __restrict__ dinv) {
    int n = blockIdx.x * blockDim.x + threadIdx.x;
    if (n < NN) dinv[n] = rsqrtf((float)(deg[n] + 1));  // +1 self loop
}
__global__ __launch_bounds__(1024) void prefix_k(const int* __restrict__ deg,
                                                 int* __restrict__ off, int* __restrict__ cur) {
    __shared__ int part[1024];
    int tid = threadIdx.x;
    int base = tid * 32;
    int s = 0;
#pragma unroll
    for (int i = 0; i < 32; i++) s += deg[base + i];
    part[tid] = s;
    __syncthreads();
    for (int d = 1; d < 1024; d <<= 1) {
        int v = (tid >= d) ? part[tid - d] : 0;
        __syncthreads();
        part[tid] += v;
        __syncthreads();
    }
    int pre = (tid > 0) ? part[tid - 1] : 0;
#pragma unroll
    for (int i = 0; i < 32; i++) {
        off[base + i] = pre;
        cur[base + i] = pre;
        pre += deg[base + i];
    }
    if (tid == 1023) off[NN] = pre;
}
__global__ void fill_k(const int* __restrict__ ei, const float* __restrict__ dinv,
                       int* __restrict__ cur, int2* __restrict__ elist) {
    int e = blockIdx.x * blockDim.x + threadIdx.x;
    if (e >= NE) return;
    int s = ei[e], d = ei[NE + e];
    float w = dinv[s] * dinv[d];
    int pos = atomicAdd(&cur[d], 1);
    elist[pos] = make_int2(s, __float_as_int(w));
}

// ---------------- SGEMM 128x64x16 double-buffered fp32 ----------------
// f32x2-packed along M; B stored pre-duplicated in smem -> no dup2 movs in inner loop.
#define TM 128
#define TN 64
#define TK 16
template <bool RELU_A, bool BIAS>
__global__ __launch_bounds__(256) void sgemm2(
    const float* __restrict__ A, const float* __restrict__ Bm,
    const float* __restrict__ bias, float* __restrict__ C,
    int M, int N, int K) {
    __shared__ float As[2][TK][TM + 4];
    __shared__ __align__(16) unsigned long long Bs2[2][TK][TN];   // (b,b) duplicated
    int tid = threadIdx.x;
    int row0 = blockIdx.y * TM, col0 = blockIdx.x * TN;
    int arow = tid >> 2, acol = (tid & 3) * 4;
    int brow = tid >> 4, bcol = (tid & 15) * 4;
    int tx = tid & 15, ty = tid >> 4;
    const float* Abase = A + (size_t)row0 * K;
    const float* Bbase = Bm + col0;

    {
        float4 a0 = *(const float4*)(Abase + (size_t)arow * K + acol);
        float4 a1 = *(const float4*)(Abase + (size_t)(arow + 64) * K + acol);
        if (RELU_A) {
            a0.x = fmaxf(a0.x, 0.f); a0.y = fmaxf(a0.y, 0.f); a0.z = fmaxf(a0.z, 0.f); a0.w = fmaxf(a0.w, 0.f);
            a1.x = fmaxf(a1.x, 0.f); a1.y = fmaxf(a1.y, 0.f); a1.z = fmaxf(a1.z, 0.f); a1.w = fmaxf(a1.w, 0.f);
        }
        As[0][acol + 0][arow] = a0.x; As[0][acol + 1][arow] = a0.y;
        As[0][acol + 2][arow] = a0.z; As[0][acol + 3][arow] = a0.w;
        As[0][acol + 0][arow + 64] = a1.x; As[0][acol + 1][arow + 64] = a1.y;
        As[0][acol + 2][arow + 64] = a1.z; As[0][acol + 3][arow + 64] = a1.w;
        float4 b = *(const float4*)(Bbase + (size_t)brow * N + bcol);
        Bs2[0][brow][bcol + 0] = dup2(b.x);
        Bs2[0][brow][bcol + 1] = dup2(b.y);
        Bs2[0][brow][bcol + 2] = dup2(b.z);
        Bs2[0][brow][bcol + 3] = dup2(b.w);
    }
    __syncthreads();

    unsigned long long acc2[4][4];
#pragma unroll
    for (int p = 0; p < 4; p++)
#pragma unroll
        for (int j = 0; j < 4; j++) acc2[p][j] = pk2(0.f, 0.f);

    int nc = K / TK;
    float4 pa0, pa1, pb;
    for (int c = 0; c < nc; c++) {
        int s = c & 1;
        if (c + 1 < nc) {
            int k0 = (c + 1) * TK;
            pa0 = *(const float4*)(Abase + (size_t)arow * K + k0 + acol);
            pa1 = *(const float4*)(Abase + (size_t)(arow + 64) * K + k0 + acol);
            pb  = *(const float4*)(Bbase + (size_t)(k0 + brow) * N + bcol);
            if (RELU_A) {
                pa0.x = fmaxf(pa0.x, 0.f); pa0.y = fmaxf(pa0.y, 0.f); pa0.z = fmaxf(pa0.z, 0.f); pa0.w = fmaxf(pa0.w, 0.f);
                pa1.x = fmaxf(pa1.x, 0.f); pa1.y = fmaxf(pa1.y, 0.f); pa1.z = fmaxf(pa1.z, 0.f); pa1.w = fmaxf(pa1.w, 0.f);
            }
        }
#pragma unroll
        for (int k = 0; k < TK; k++) {
            ulonglong2 a0p = *(const ulonglong2*)&As[s][k][ty * 8];
            ulonglong2 a1p = *(const ulonglong2*)&As[s][k][ty * 8 + 4];
            ulonglong2 b01 = *(const ulonglong2*)&Bs2[s][k][tx * 4];
            ulonglong2 b23 = *(const ulonglong2*)&Bs2[s][k][tx * 4 + 2];
            fma2(acc2[0][0], a0p.x, b01.x); fma2(acc2[0][1], a0p.x, b01.y);
            fma2(acc2[0][2], a0p.x, b23.x); fma2(acc2[0][3], a0p.x, b23.y);
            fma2(acc2[1][0], a0p.y, b01.x); fma2(acc2[1][1], a0p.y, b01.y);
            fma2(acc2[1][2], a0p.y, b23.x); fma2(acc2[1][3], a0p.y, b23.y);
            fma2(acc2[2][0], a1p.x, b01.x); fma2(acc2[2][1], a1p.x, b01.y);
            fma2(acc2[2][2], a1p.x, b23.x); fma2(acc2[2][3], a1p.x, b23.y);
            fma2(acc2[3][0], a1p.y, b01.x); fma2(acc2[3][1], a1p.y, b01.y);
            fma2(acc2[3][2], a1p.y, b23.x); fma2(acc2[3][3], a1p.y, b23.y);
        }
        if (c + 1 < nc) {
            int d = s ^ 1;
            As[d][acol + 0][arow] = pa0.x; As[d][acol + 1][arow] = pa0.y;
            As[d][acol + 2][arow] = pa0.z; As[d][acol + 3][arow] = pa0.w;
            As[d][acol + 0][arow + 64] = pa1.x; As[d][acol + 1][arow + 64] = pa1.y;
            As[d][acol + 2][arow + 64] = pa1.z; As[d][acol + 3][arow + 64] = pa1.w;
            Bs2[d][brow][bcol + 0] = dup2(pb.x);
            Bs2[d][brow][bcol + 1] = dup2(pb.y);
            Bs2[d][brow][bcol + 2] = dup2(pb.z);
            Bs2[d][brow][bcol + 3] = dup2(pb.w);
        }
        __syncthreads();
    }

    float4 bv = make_float4(0.f, 0.f, 0.f, 0.f);
    if (BIAS) bv = *(const float4*)(bias + col0 + tx * 4);
#pragma unroll
    for (int p = 0; p < 4; p++) {
        float lo[4], hi[4];
#pragma unroll
        for (int j = 0; j < 4; j++) upk2(acc2[p][j], lo[j], hi[j]);
        *(float4*)(C + (size_t)(row0 + ty * 8 + 2 * p) * N + col0 + tx * 4) =
            make_float4(lo[0] + bv.x, lo[1] + bv.y, lo[2] + bv.z, lo[3] + bv.w);
        *(float4*)(C + (size_t)(row0 + ty * 8 + 2 * p + 1) * N + col0 + tx * 4) =
            make_float4(hi[0] + bv.x, hi[1] + bv.y, hi[2] + bv.z, hi[3] + bv.w);
    }
}

// ---------------- GCN gather (no atomics): out[n] = bias + dinv[n]^2*xw[n] + sum_e w*xw[src] ----------------
template <int C4>
__global__ void gather_k(const float* __restrict__ xw, const int2* __restrict__ elist,
                         const int* __restrict__ off, const float* __restrict__ bias,
                         const float* __restrict__ dinv, float* __restrict__ out) {
    int idx = blockIdx.x * blockDim.x + threadIdx.x;
    if (idx >= NN * C4) return;
    int n = idx / C4, cc = idx % C4;
    const int C = C4 * 4;
    float di = dinv[n];
    float d2 = di * di;
    float4 bv = *(const float4*)(bias + cc * 4);
    float4 sv = *(const float4*)(xw + (size_t)n * C + cc * 4);
    float4 acc = make_float4(bv.x + d2 * sv.x, bv.y + d2 * sv.y,
                             bv.z + d2 * sv.z, bv.w + d2 * sv.w);
    int e0 = off[n], e1 = off[n + 1];
    for (int i = e0; i < e1; i++) {
        int2 e = __ldg(&elist[i]);
        float w = __int_as_float(e.y);
        float4 v = *(const float4*)(xw + (size_t)e.x * C + cc * 4);
        acc.x = fmaf(w, v.x, acc.x);
        acc.y = fmaf(w, v.y, acc.y);
        acc.z = fmaf(w, v.z, acc.z);
        acc.w = fmaf(w, v.w, acc.w);
    }
    *(float4*)(out + (size_t)n * C + cc * 4) = acc;
}

// ---------------- LSTM: cluster-of-4 K-split, reg weights, f32x2-packed recurrence (proven R11) ----------------
__global__ __launch_bounds__(768, 1) __cluster_dims__(4, 1, 1)
void lstm_cluster_kernel(const float* __restrict__ xih, const float* __restrict__ whhT,
                         float* __restrict__ out) {
    __shared__ __align__(16) float2 h01[192];
    __shared__ __align__(16) float2 gb[4 * 192];
    __shared__ float2 xs[2][768];
    float wreg[48];
    int tid = threadIdx.x;
    uint32_t rank;
    asm("mov.u32 %0, %%cluster_ctarank;" : "=r"(rank));
    int b0 = (blockIdx.x >> 2) * 2;

#pragma unroll
    for (int k = 0; k < 48; k++)
        wreg[k] = whhT[(size_t)(rank * 48 + k) * 768 + tid];
    if (tid < 192) h01[tid] = make_float2(0.f, 0.f);

    int gidx = tid / 192, u192 = tid % 192;
    uint32_t ro = (uint32_t)(u192 / 48);
    int slot = gidx * 48 + (u192 % 48);
    uint32_t gb_local = smem_u32(&gb[rank * 192 + slot]);
    uint32_t gb_remote;
    asm("mapa.shared::cluster.u32 %0, %1, %2;" : "=r"(gb_remote) : "r"(gb_local), "r"(ro));

    float2 c01 = make_float2(0.f, 0.f);
    int unit = rank * 48 + tid;
    uint32_t hrem[4];
    if (tid < 48) {
        uint32_t hl = smem_u32(&h01[unit]);
#pragma unroll
        for (uint32_t rr = 0; rr < 4; rr++)
            asm("mapa.shared::cluster.u32 %0, %1, %2;" : "=r"(hrem[rr]) : "r"(hl), "r"(rr));
    }
    const float* x0 = xih + (size_t)b0 * SS * H4;
    const float* x1 = x0 + (size_t)SS * H4;
    float* o0 = out + (size_t)b0 * SS * OC;
    float* o1 = o0 + (size_t)SS * OC;
    const int hb = (int)rank * 48;

    xs[0][tid] = make_float2(x0[tid], x1[tid]);

    CLUSTER_SYNC();
    for (int t = 0; t < SS; t++) {
        unsigned long long acc = pk2(0.f, 0.f);
#pragma unroll
        for (int p = 0; p < 24; p++) {
            ulonglong2 hv = *(const ulonglong2*)&h01[hb + 2 * p];
            fma2(acc, dup2(wreg[2 * p]),     hv.x);
            fma2(acc, dup2(wreg[2 * p + 1]), hv.y);
        }
        asm volatile("st.shared::cluster.b64 [%0], %1;" :: "r"(gb_remote), "l"(acc) : "memory");
        float nx0 = 0.f, nx1 = 0.f;
        bool pf = (t + 1 < SS);
        if (pf) {
            nx0 = x0[(size_t)(t + 1) * H4 + tid];
            nx1 = x1[(size_t)(t + 1) * H4 + tid];
        }
        CLUSTER_SYNC();
        if (pf) xs[(t + 1) & 1][tid] = make_float2(nx0, nx1);
        if (tid < 48) {
            const float2* xrow = xs[t & 1];
            float pre0[4], pre1[4];
#pragma unroll
            for (int g = 0; g < 4; g++) {
                float2 s0 = gb[0 * 192 + g * 48 + tid];
                float2 s1 = gb[1 * 192 + g * 48 + tid];
                float2 s2 = gb[2 * 192 + g * 48 + tid];
                float2 s3 = gb[3 * 192 + g * 48 + tid];
                float2 xg = xrow[g * 192 + unit];
                pre0[g] = s0.x + s1.x + s2.x + s3.x + xg.x;
                pre1[g] = s0.y + s1.y + s2.y + s3.y + xg.y;
            }
            float i0 = sigf(pre0[0]), f0 = sigf(pre0[1]), g0 = tanhf(pre0[2]), oo0 = sigf(pre0[3]);
            float i1 = sigf(pre1[0]), f1 = sigf(pre1[1]), g1 = tanhf(pre1[2]), oo1 = sigf(pre1[3]);
            c01.x = f0 * c01.x + i0 * g0;
            c01.y = f1 * c01.y + i1 * g1;
            float h0v = oo0 * tanhf(c01.x);
            float h1v = oo1 * tanhf(c01.y);
            unsigned long long hp = pk2(h0v, h1v);
#pragma unroll
            for (int rr = 0; rr < 4; rr++)
                asm volatile("st.shared::cluster.b64 [%0], %1;" :: "r"(hrem[rr]), "l"(hp) : "memory");
            o0[(size_t)t * OC + unit] = h0v;
            o1[(size_t)t * OC + unit] = h1v;
        }
        CLUSTER_SYNC();
    }
}

// ---------------- attention: one CTA per (b, head), 4 q-rows per warp, f32x2-packed math ----------------
#define AT_SMEM (16 * 512 * 4 * 4)
__global__ __launch_bounds__(256, 1) void attn_kernel(
    const float* __restrict__ qkv, float* __restrict__ outp) {
    extern __shared__ float sm[];
    int bh = blockIdx.x;
    int b = bh / 6, h = bh % 6;
    int tid = threadIdx.x;
    const float* base = qkv + (size_t)b * SS * QC + h * 32;
    for (int i = tid; i < SS * 8; i += 256) {
        int c = i >> 9, r = i & 511;
        float4 kv = *(const float4*)(base + (size_t)r * QC + 192 + c * 4);
        float4 vv = *(const float4*)(base + (size_t)r * QC + 384 + c * 4);
        *(float4*)(sm + ((c * 512 + r) << 2)) = kv;
        *(float4*)(sm + (((8 + c) * 512 + r) << 2)) = vv;
    }
    __syncthreads();
    int wid = tid >> 5, lane = tid & 31;
    const float scale = 0.17677669529663689f;  // 1/sqrt(32)
    for (int g = 0; g < 16; g++) {
        int q0 = (g * 8 + wid) * 4;
        float s[4][16];
#pragma unroll
        for (int r = 0; r < 4; r++)
#pragma unroll
            for (int jj = 0; jj < 16; jj++) s[r][jj] = 0.f;
#pragma unroll
        for (int dh = 0; dh < 2; dh++) {
            unsigned long long qp[4][8];
#pragma unroll
            for (int r = 0; r < 4; r++)
#pragma unroll
                for (int c = 0; c < 4; c++) {
                    float4 t = *(const float4*)(base + (size_t)(q0 + r) * QC + dh * 16 + c * 4);
                    qp[r][c * 2 + 0] = pk2(t.x * scale, t.y * scale);
                    qp[r][c * 2 + 1] = pk2(t.z * scale, t.w * scale);
                }
            for (int jj = 0; jj < 16; jj++) {
                int krow = jj * 32 + lane;
                unsigned long long a2[4];
#pragma unroll
                for (int r = 0; r < 4; r++) a2[r] = pk2(0.f, 0.f);
#pragma unroll
                for (int c = 0; c < 4; c++) {
                    ulonglong2 kp = *(const ulonglong2*)(sm + (((dh * 4 + c) * 512 + krow) << 2));
#pragma unroll
                    for (int r = 0; r < 4; r++) {
                        fma2(a2[r], qp[r][c * 2 + 0], kp.x);
                        fma2(a2[r], qp[r][c * 2 + 1], kp.y);
                    }
                }
#pragma unroll
                for (int r = 0; r < 4; r++) {
                    float lo, hi;
                    upk2(a2[r], lo, hi);
                    s[r][jj] += lo + hi;
                }
            }
        }
        float inv[4];
#pragma unroll
        for (int r = 0; r < 4; r++) {
            float mx = -1e30f;
#pragma unroll
            for (int jj = 0; jj < 16; jj++) mx = fmaxf(mx, s[r][jj]);
#pragma unroll
            for (int off = 16; off; off >>= 1) mx = fmaxf(mx, __shfl_xor_sync(0xffffffffu, mx, off));
            float sum = 0.f;
#pragma unroll
            for (int jj = 0; jj < 16; jj++) { s[r][jj] = __expf(s[r][jj] - mx); sum += s[r][jj]; }
#pragma unroll
            for (int off = 16; off; off >>= 1) sum += __shfl_xor_sync(0xffffffffu, sum, off);
            inv[r] = 1.0f / sum;
        }
#pragma unroll
        for (int dh = 0; dh < 2; dh++) {
            unsigned long long o2[4][8];
#pragma unroll
            for (int r = 0; r < 4; r++)
#pragma unroll
                for (int d = 0; d < 8; d++) o2[r][d] = pk2(0.f, 0.f);
            for (int jj = 0; jj < 16; jj++) {
                int vrow = jj * 32 + lane;
                unsigned long long pd[4];
#pragma unroll
                for (int r = 0; r < 4; r++) pd[r] = dup2(s[r][jj]);
#pragma unroll
                for (int c = 0; c < 4; c++) {
                    ulonglong2 vp = *(const ulonglong2*)(sm + (((8 + dh * 4 + c) * 512 + vrow) << 2));
#pragma unroll
                    for (int r = 0; r < 4; r++) {
                        fma2(o2[r][c * 2 + 0], pd[r], vp.x);
                        fma2(o2[r][c * 2 + 1], pd[r], vp.y);
                    }
                }
            }
#pragma unroll
            for (int r = 0; r < 4; r++) {
                float o[16];
#pragma unroll
                for (int d = 0; d < 8; d++) upk2(o2[r][d], o[2 * d], o[2 * d + 1]);
#pragma unroll
                for (int d = 0; d < 16; d++) {
                    float v = o[d];
                    v += __shfl_down_sync(0xffffffffu, v, 16);
                    v += __shfl_down_sync(0xffffffffu, v, 8);
                    v += __shfl_down_sync(0xffffffffu, v, 4);
                    v += __shfl_down_sync(0xffffffffu, v, 2);
                    v += __shfl_down_sync(0xffffffffu, v, 1);
                    o[d] = v;
                }
                if (lane == 0) {
                    float* orow = outp + (size_t)(b * SS + q0 + r) * OC + h * 32 + dh * 16;
                    float iv = inv[r];
#pragma unroll
                    for (int c = 0; c < 4; c++)
                        *(float4*)(orow + c * 4) = make_float4(
                            o[c * 4 + 0] * iv, o[c * 4 + 1] * iv,
                            o[c * 4 + 2] * iv, o[c * 4 + 3] * iv);
                }
            }
        }
    }
}

// ---------------- fused mean over time + final projection ----------------
__global__ void mean_proj_k(const float* __restrict__ attn, const float* __restrict__ W,
                            const float* __restrict__ bias, float* __restrict__ out) {
    __shared__ float sx[OC];
    int b = blockIdx.x, c = threadIdx.x;  // 192 threads
    float s = 0.f;
    for (int t = 0; t < SS; t++) s += attn[(size_t)(b * SS + t) * OC + c];
    sx[c] = s * (1.0f / SS);
    __syncthreads();
    float acc = 0.f;
    const float* wr = W + c * OC;
    for (int k = 0; k < OC; k++) acc += sx[k] * wr[k];
    out[b * OC + c] = acc + bias[c];
}

// ---------------- launch ----------------
extern "C" void kernel_launch(void* const* d_in, const int* in_sizes, int n_in,
                              void* d_out, int out_size) {
    const float* x    = (const float*)d_in[0];
    const int*   ei   = (const int*)d_in[1];
    const float* W0   = (const float*)d_in[3];
    const float* b0   = (const float*)d_in[4];
    const float* W1   = (const float*)d_in[5];
    const float* b1   = (const float*)d_in[6];
    const float* W2   = (const float*)d_in[7];
    const float* b2   = (const float*)d_in[8];
    const float* wih  = (const float*)d_in[9];
    const float* whh  = (const float*)d_in[10];
    const float* bih  = (const float*)d_in[11];
    const float* bhh  = (const float*)d_in[12];
    const float* inW  = (const float*)d_in[13];
    const float* inB  = (const float*)d_in[14];
    const float* outW = (const float*)d_in[15];
    const float* outB = (const float*)d_in[16];
    float* out = (float*)d_out;

    float *xw, *hA, *hB, *xih, *lstm, *qkv, *attn, *dinv, *wihT, *whhT, *inT, *gbias;
    int *deg, *off, *cur;
    int2* elist;
    cudaGetSymbolAddress((void**)&xw, g_xw);
    cudaGetSymbolAddress((void**)&hA, g_hA);
    cudaGetSymbolAddress((void**)&hB, g_hB);
    cudaGetSymbolAddress((void**)&xih, g_xih);
    cudaGetSymbolAddress((void**)&lstm, g_lstm);
    cudaGetSymbolAddress((void**)&qkv, g_qkv);
    cudaGetSymbolAddress((void**)&attn, g_attn);
    cudaGetSymbolAddress((void**)&dinv, g_dinv);
    cudaGetSymbolAddress((void**)&deg, g_deg);
    cudaGetSymbolAddress((void**)&off, g_off);
    cudaGetSymbolAddress((void**)&cur, g_cur);
    cudaGetSymbolAddress((void**)&elist, g_elist);
    cudaGetSymbolAddress((void**)&wihT, g_wihT);
    cudaGetSymbolAddress((void**)&whhT, g_whhT);
    cudaGetSymbolAddress((void**)&inT, g_inT);
    cudaGetSymbolAddress((void**)&gbias, g_gbias);

    cudaFuncSetAttribute(attn_kernel, cudaFuncAttributeMaxDynamicSharedMemorySize, AT_SMEM);

    // prep (layer-1 GEMM at slot 3 so ncu captures it)
    const int PREP_N = 2 * H4 * 192 + QC * 192 + H4;
    prep_k<<<(PREP_N + 255) / 256, 256>>>(wih, whh, inW, bih, bhh, wihT, whhT, inT, gbias);
    zero_i32_k<<<(NN + 255) / 256, 256>>>(deg, NN);
    count_deg_k<<<(NE + 255) / 256, 256>>>(ei, deg);
    sgemm2<false, false><<<dim3(128 / TN, NN / TM), 256>>>(x, W0, nullptr, xw, NN, 128, 128);
    calc_dinv_k<<<(NN + 255) / 256, 256>>>(deg, dinv);
    prefix_k<<<1, 1024>>>(deg, off, cur);
    fill_k<<<(NE + 255) / 256, 256>>>(ei, dinv, cur, elist);

    gather_k<32><<<(NN * 32 + 255) / 256, 256>>>(xw, elist, off, b0, dinv, hA);
    // GCN layer 2
    sgemm2<true, false><<<dim3(128 / TN, NN / TM), 256>>>(hA, W1, nullptr, xw, NN, 128, 128);
    gather_k<32><<<(NN * 32 + 255) / 256, 256>>>(xw, elist, off, b1, dinv, hB);
    // GCN layer 3
    sgemm2<true, false><<<dim3(192 / TN, NN / TM), 256>>>(hB, W2, nullptr, xw, NN, 192, 128);
    gather_k<48><<<(NN * 48 + 255) / 256, 256>>>(xw, elist, off, b2, dinv, hA);

    // LSTM input precompute + recurrence
    sgemm2<true, true><<<dim3(H4 / TN, NN / TM), 256>>>(hA, wihT, gbias, xih, NN, H4, 192);
    lstm_cluster_kernel<<<128, 768>>>(xih, whhT, lstm);
    // QKV projection
    sgemm2<false, true><<<dim3(QC / TN, NN / TM), 256>>>(lstm, inT, inB, qkv, NN, QC, 192);
    // attention
    attn_kernel<<<BB * 6, 256, AT_SMEM>>>(qkv, attn);
    // fused mean + output projection
    mean_proj_k<<<BB, OC>>>(attn, outW, outB, out);
}

// round 15
// speedup vs baseline: 1.8936x; 1.1813x over previous
#include <cuda_runtime.h>
#include <cstdint>
#include <cstddef>

#define NN 32768
#define NE 327680
#define BB 64
#define SS 512
#define OC 192
#define H4 768
#define QC 576

// ---------------- scratch (static device globals; no allocations) ----------------
__device__ float g_xw  [NN * 192];
__device__ float g_hA  [NN * 192];
__device__ float g_hB  [NN * 192];
__device__ float g_xih [(size_t)NN * H4];
__device__ float g_lstm[NN * OC];
__device__ float g_qkv [NN * QC];
__device__ float g_attn[NN * OC];
__device__ float g_dinv[NN];
__device__ int   g_deg [NN];
__device__ int   g_off [NN + 1];
__device__ int   g_cur [NN];
__device__ int2  g_elist[NE];
__device__ float g_wihT[192 * H4];
__device__ float g_whhT[192 * H4];
__device__ float g_inT [192 * QC];
__device__ float g_gbias[H4];

// ---------------- small helpers ----------------
__device__ __forceinline__ unsigned long long pk2(float a, float b) {
    unsigned long long r;
    asm("mov.b64 %0, {%1,%2};" : "=l"(r) : "f"(a), "f"(b));
    return r;
}
__device__ __forceinline__ void upk2(unsigned long long v, float& a, float& b) {
    asm("mov.b64 {%0,%1}, %2;" : "=f"(a), "=f"(b) : "l"(v));
}
__device__ __forceinline__ unsigned long long dup2(float w) {
    unsigned long long r;
    asm volatile("mov.b64 %0, {%1,%1};" : "=l"(r) : "f"(w));
    return r;
}
__device__ __forceinline__ void fma2(unsigned long long& acc, unsigned long long a, unsigned long long b) {
    asm("fma.rn.f32x2 %0, %1, %2, %0;" : "+l"(acc) : "l"(a), "l"(b));
}
__device__ __forceinline__ float sigf(float x) { return 1.0f / (1.0f + __expf(-x)); }
__device__ __forceinline__ uint32_t smem_u32(const void* p) {
    uint32_t a;
    asm("{ .reg .u64 t; cvta.to.shared.u64 t, %1; cvt.u32.u64 %0, t; }" : "=r"(a) : "l"(p));
    return a;
}
#define CLUSTER_SYNC() do { \
    asm volatile("barrier.cluster.arrive.aligned;" ::: "memory"); \
    asm volatile("barrier.cluster.wait.aligned;" ::: "memory"); \
} while (0)

// ---------------- fused prep: 3 transposes + lstm bias ----------------
__global__ void prep_k(const float* __restrict__ wih, const float* __restrict__ whh,
                       const float* __restrict__ inW, const float* __restrict__ bih,
                       const float* __restrict__ bhh,
                       float* __restrict__ wihT, float* __restrict__ whhT,
                       float* __restrict__ inT, float* __restrict__ gbias) {
    int idx = blockIdx.x * blockDim.x + threadIdx.x;
    const int T1 = H4 * 192;
    const int T2 = 2 * T1;
    const int T3 = T2 + QC * 192;
    const int T4 = T3 + H4;
    if (idx < T1) {
        int r = idx / 192, c = idx % 192;
        wihT[c * H4 + r] = wih[idx];
    } else if (idx < T2) {
        int j = idx - T1;
        int r = j / 192, c = j % 192;
        whhT[c * H4 + r] = whh[j];
    } else if (idx < T3) {
        int j = idx - T2;
        int r = j / 192, c = j % 192;
        inT[c * QC + r] = inW[j];
    } else if (idx < T4) {
        int j = idx - T3;
        gbias[j] = bih[j] + bhh[j];
    }
}
__global__ void zero_i32_k(int* p, int n) {
    int i = blockIdx.x * blockDim.x + threadIdx.x;
    if (i < n) p[i] = 0;
}
__global__ void count_deg_k(const int* __restrict__ ei, int* __restrict__ deg) {
    int e = blockIdx.x * blockDim.x + threadIdx.x;
    if (e < NE) atomicAdd(&deg[ei[NE + e]], 1);
}
__global__ void calc_dinv_k(const int* __restrict__ deg, float* __restrict__ dinv) {
    int n = blockIdx.x * blockDim.x + threadIdx.x;
    if (n < NN) dinv[n] = rsqrtf((float)(deg[n] + 1));  // +1 self loop
}
__global__ __launch_bounds__(1024) void prefix_k(const int* __restrict__ deg,
                                                 int* __restrict__ off, int* __restrict__ cur) {
    __shared__ int part[1024];
    int tid = threadIdx.x;
    int base = tid * 32;
    int s = 0;
#pragma unroll
    for (int i = 0; i < 32; i++) s += deg[base + i];
    part[tid] = s;
    __syncthreads();
    for (int d = 1; d < 1024; d <<= 1) {
        int v = (tid >= d) ? part[tid - d] : 0;
        __syncthreads();
        part[tid] += v;
        __syncthreads();
    }
    int pre = (tid > 0) ? part[tid - 1] : 0;
#pragma unroll
    for (int i = 0; i < 32; i++) {
        off[base + i] = pre;
        cur[base + i] = pre;
        pre += deg[base + i];
    }
    if (tid == 1023) off[NN] = pre;
}
__global__ void fill_k(const int* __restrict__ ei, const float* __restrict__ dinv,
                       int* __restrict__ cur, int2* __restrict__ elist) {
    int e = blockIdx.x * blockDim.x + threadIdx.x;
    if (e >= NE) return;
    int s = ei[e], d = ei[NE + e];
    float w = dinv[s] * dinv[d];
    int pos = atomicAdd(&cur[d], 1);
    elist[pos] = make_int2(s, __float_as_int(w));
}

// ---------------- SGEMM 128x64x16 double-buffered fp32, f32x2-packed along M (proven R11) ----------------
#define TM 128
#define TN 64
#define TK 16
template <bool RELU_A, bool BIAS>
__global__ __launch_bounds__(256, 3) void sgemm2(
    const float* __restrict__ A, const float* __restrict__ Bm,
    const float* __restrict__ bias, float* __restrict__ C,
    int M, int N, int K) {
    __shared__ float As[2][TK][TM + 4];
    __shared__ float Bs[2][TK][TN];
    int tid = threadIdx.x;
    int row0 = blockIdx.y * TM, col0 = blockIdx.x * TN;
    int arow = tid >> 2, acol = (tid & 3) * 4;
    int brow = tid >> 4, bcol = (tid & 15) * 4;
    int tx = tid & 15, ty = tid >> 4;
    const float* Abase = A + (size_t)row0 * K;
    const float* Bbase = Bm + col0;

    {
        float4 a0 = *(const float4*)(Abase + (size_t)arow * K + acol);
        float4 a1 = *(const float4*)(Abase + (size_t)(arow + 64) * K + acol);
        if (RELU_A) {
            a0.x = fmaxf(a0.x, 0.f); a0.y = fmaxf(a0.y, 0.f); a0.z = fmaxf(a0.z, 0.f); a0.w = fmaxf(a0.w, 0.f);
            a1.x = fmaxf(a1.x, 0.f); a1.y = fmaxf(a1.y, 0.f); a1.z = fmaxf(a1.z, 0.f); a1.w = fmaxf(a1.w, 0.f);
        }
        As[0][acol + 0][arow] = a0.x; As[0][acol + 1][arow] = a0.y;
        As[0][acol + 2][arow] = a0.z; As[0][acol + 3][arow] = a0.w;
        As[0][acol + 0][arow + 64] = a1.x; As[0][acol + 1][arow + 64] = a1.y;
        As[0][acol + 2][arow + 64] = a1.z; As[0][acol + 3][arow + 64] = a1.w;
        *(float4*)&Bs[0][brow][bcol] = *(const float4*)(Bbase + (size_t)brow * N + bcol);
    }
    __syncthreads();

    unsigned long long acc2[4][4];
#pragma unroll
    for (int p = 0; p < 4; p++)
#pragma unroll
        for (int j = 0; j < 4; j++) acc2[p][j] = pk2(0.f, 0.f);

    int nc = K / TK;
    float4 pa0, pa1, pb;
    for (int c = 0; c < nc; c++) {
        int s = c & 1;
        if (c + 1 < nc) {
            int k0 = (c + 1) * TK;
            pa0 = *(const float4*)(Abase + (size_t)arow * K + k0 + acol);
            pa1 = *(const float4*)(Abase + (size_t)(arow + 64) * K + k0 + acol);
            pb  = *(const float4*)(Bbase + (size_t)(k0 + brow) * N + bcol);
            if (RELU_A) {
                pa0.x = fmaxf(pa0.x, 0.f); pa0.y = fmaxf(pa0.y, 0.f); pa0.z = fmaxf(pa0.z, 0.f); pa0.w = fmaxf(pa0.w, 0.f);
                pa1.x = fmaxf(pa1.x, 0.f); pa1.y = fmaxf(pa1.y, 0.f); pa1.z = fmaxf(pa1.z, 0.f); pa1.w = fmaxf(pa1.w, 0.f);
            }
        }
#pragma unroll
        for (int k = 0; k < TK; k++) {
            ulonglong2 a0p = *(const ulonglong2*)&As[s][k][ty * 8];
            ulonglong2 a1p = *(const ulonglong2*)&As[s][k][ty * 8 + 4];
            float4 bv = *(const float4*)&Bs[s][k][tx * 4];
            unsigned long long bp0 = dup2(bv.x), bp1 = dup2(bv.y);
            unsigned long long bp2 = dup2(bv.z), bp3 = dup2(bv.w);
            fma2(acc2[0][0], a0p.x, bp0); fma2(acc2[0][1], a0p.x, bp1);
            fma2(acc2[0][2], a0p.x, bp2); fma2(acc2[0][3], a0p.x, bp3);
            fma2(acc2[1][0], a0p.y, bp0); fma2(acc2[1][1], a0p.y, bp1);
            fma2(acc2[1][2], a0p.y, bp2); fma2(acc2[1][3], a0p.y, bp3);
            fma2(acc2[2][0], a1p.x, bp0); fma2(acc2[2][1], a1p.x, bp1);
            fma2(acc2[2][2], a1p.x, bp2); fma2(acc2[2][3], a1p.x, bp3);
            fma2(acc2[3][0], a1p.y, bp0); fma2(acc2[3][1], a1p.y, bp1);
            fma2(acc2[3][2], a1p.y, bp2); fma2(acc2[3][3], a1p.y, bp3);
        }
        if (c + 1 < nc) {
            int d = s ^ 1;
            As[d][acol + 0][arow] = pa0.x; As[d][acol + 1][arow] = pa0.y;
            As[d][acol + 2][arow] = pa0.z; As[d][acol + 3][arow] = pa0.w;
            As[d][acol + 0][arow + 64] = pa1.x; As[d][acol + 1][arow + 64] = pa1.y;
            As[d][acol + 2][arow + 64] = pa1.z; As[d][acol + 3][arow + 64] = pa1.w;
            *(float4*)&Bs[d][brow][bcol] = pb;
        }
        __syncthreads();
    }

    float4 bv = make_float4(0.f, 0.f, 0.f, 0.f);
    if (BIAS) bv = *(const float4*)(bias + col0 + tx * 4);
#pragma unroll
    for (int p = 0; p < 4; p++) {
        float lo[4], hi[4];
#pragma unroll
        for (int j = 0; j < 4; j++) upk2(acc2[p][j], lo[j], hi[j]);
        *(float4*)(C + (size_t)(row0 + ty * 8 + 2 * p) * N + col0 + tx * 4) =
            make_float4(lo[0] + bv.x, lo[1] + bv.y, lo[2] + bv.z, lo[3] + bv.w);
        *(float4*)(C + (size_t)(row0 + ty * 8 + 2 * p + 1) * N + col0 + tx * 4) =
            make_float4(hi[0] + bv.x, hi[1] + bv.y, hi[2] + bv.z, hi[3] + bv.w);
    }
}

// ---------------- GCN gather (no atomics): out[n] = bias + dinv[n]^2*xw[n] + sum_e w*xw[src] ----------------
template <int C4>
__global__ void gather_k(const float* __restrict__ xw, const int2* __restrict__ elist,
                         const int* __restrict__ off, const float* __restrict__ bias,
                         const float* __restrict__ dinv, float* __restrict__ out) {
    int idx = blockIdx.x * blockDim.x + threadIdx.x;
    if (idx >= NN * C4) return;
    int n = idx / C4, cc = idx % C4;
    const int C = C4 * 4;
    float di = dinv[n];
    float d2 = di * di;
    float4 bv = *(const float4*)(bias + cc * 4);
    float4 sv = *(const float4*)(xw + (size_t)n * C + cc * 4);
    float4 acc = make_float4(bv.x + d2 * sv.x, bv.y + d2 * sv.y,
                             bv.z + d2 * sv.z, bv.w + d2 * sv.w);
    int e0 = off[n], e1 = off[n + 1];
    for (int i = e0; i < e1; i++) {
        int2 e = __ldg(&elist[i]);
        float w = __int_as_float(e.y);
        float4 v = *(const float4*)(xw + (size_t)e.x * C + cc * 4);
        acc.x = fmaf(w, v.x, acc.x);
        acc.y = fmaf(w, v.y, acc.y);
        acc.z = fmaf(w, v.z, acc.z);
        acc.w = fmaf(w, v.w, acc.w);
    }
    *(float4*)(out + (size_t)n * C + cc * 4) = acc;
}

// ---------------- LSTM: cluster-of-4 K-split, reg weights, f32x2-packed recurrence (proven R8/R11) ----------------
__global__ __launch_bounds__(768, 1) __cluster_dims__(4, 1, 1)
void lstm_cluster_kernel(const float* __restrict__ xih, const float* __restrict__ whhT,
                         float* __restrict__ out) {
    __shared__ __align__(16) float2 h01[192];
    __shared__ __align__(16) float2 gb[4 * 192];
    __shared__ float2 xs[2][768];
    float wreg[48];
    int tid = threadIdx.x;
    uint32_t rank;
    asm("mov.u32 %0, %%cluster_ctarank;" : "=r"(rank));
    int b0 = (blockIdx.x >> 2) * 2;

#pragma unroll
    for (int k = 0; k < 48; k++)
        wreg[k] = whhT[(size_t)(rank * 48 + k) * 768 + tid];
    if (tid < 192) h01[tid] = make_float2(0.f, 0.f);

    int gidx = tid / 192, u192 = tid % 192;
    uint32_t ro = (uint32_t)(u192 / 48);
    int slot = gidx * 48 + (u192 % 48);
    uint32_t gb_local = smem_u32(&gb[rank * 192 + slot]);
    uint32_t gb_remote;
    asm("mapa.shared::cluster.u32 %0, %1, %2;" : "=r"(gb_remote) : "r"(gb_local), "r"(ro));

    float2 c01 = make_float2(0.f, 0.f);
    int unit = rank * 48 + tid;
    uint32_t hrem[4];
    if (tid < 48) {
        uint32_t hl = smem_u32(&h01[unit]);
#pragma unroll
        for (uint32_t rr = 0; rr < 4; rr++)
            asm("mapa.shared::cluster.u32 %0, %1, %2;" : "=r"(hrem[rr]) : "r"(hl), "r"(rr));
    }
    const float* x0 = xih + (size_t)b0 * SS * H4;
    const float* x1 = x0 + (size_t)SS * H4;
    float* o0 = out + (size_t)b0 * SS * OC;
    float* o1 = o0 + (size_t)SS * OC;
    const int hb = (int)rank * 48;

    xs[0][tid] = make_float2(x0[tid], x1[tid]);

    CLUSTER_SYNC();
    for (int t = 0; t < SS; t++) {
        unsigned long long acc = pk2(0.f, 0.f);
#pragma unroll
        for (int p = 0; p < 24; p++) {
            ulonglong2 hv = *(const ulonglong2*)&h01[hb + 2 * p];
            fma2(acc, dup2(wreg[2 * p]),     hv.x);
            fma2(acc, dup2(wreg[2 * p + 1]), hv.y);
        }
        asm volatile("st.shared::cluster.b64 [%0], %1;" :: "r"(gb_remote), "l"(acc) : "memory");
        float nx0 = 0.f, nx1 = 0.f;
        bool pf = (t + 1 < SS);
        if (pf) {
            nx0 = x0[(size_t)(t + 1) * H4 + tid];
            nx1 = x1[(size_t)(t + 1) * H4 + tid];
        }
        CLUSTER_SYNC();
        if (pf) xs[(t + 1) & 1][tid] = make_float2(nx0, nx1);
        if (tid < 48) {
            const float2* xrow = xs[t & 1];
            float pre0[4], pre1[4];
#pragma unroll
            for (int g = 0; g < 4; g++) {
                float2 s0 = gb[0 * 192 + g * 48 + tid];
                float2 s1 = gb[1 * 192 + g * 48 + tid];
                float2 s2 = gb[2 * 192 + g * 48 + tid];
                float2 s3 = gb[3 * 192 + g * 48 + tid];
                float2 xg = xrow[g * 192 + unit];
                pre0[g] = s0.x + s1.x + s2.x + s3.x + xg.x;
                pre1[g] = s0.y + s1.y + s2.y + s3.y + xg.y;
            }
            float i0 = sigf(pre0[0]), f0 = sigf(pre0[1]), g0 = tanhf(pre0[2]), oo0 = sigf(pre0[3]);
            float i1 = sigf(pre1[0]), f1 = sigf(pre1[1]), g1 = tanhf(pre1[2]), oo1 = sigf(pre1[3]);
            c01.x = f0 * c01.x + i0 * g0;
            c01.y = f1 * c01.y + i1 * g1;
            float h0v = oo0 * tanhf(c01.x);
            float h1v = oo1 * tanhf(c01.y);
            unsigned long long hp = pk2(h0v, h1v);
#pragma unroll
            for (int rr = 0; rr < 4; rr++)
                asm volatile("st.shared::cluster.b64 [%0], %1;" :: "r"(hrem[rr]), "l"(hp) : "memory");
            o0[(size_t)t * OC + unit] = h0v;
            o1[(size_t)t * OC + unit] = h1v;
        }
        CLUSTER_SYNC();
    }
}

// ---------------- attention: one CTA per (b, head), 4 q-rows per warp, f32x2-packed math ----------------
#define AT_SMEM (16 * 512 * 4 * 4)
__global__ __launch_bounds__(256, 1) void attn_kernel(
    const float* __restrict__ qkv, float* __restrict__ outp) {
    extern __shared__ float sm[];
    int bh = blockIdx.x;
    int b = bh / 6, h = bh % 6;
    int tid = threadIdx.x;
    const float* base = qkv + (size_t)b * SS * QC + h * 32;
    for (int i = tid; i < SS * 8; i += 256) {
        int c = i >> 9, r = i & 511;
        float4 kv = *(const float4*)(base + (size_t)r * QC + 192 + c * 4);
        float4 vv = *(const float4*)(base + (size_t)r * QC + 384 + c * 4);
        *(float4*)(sm + ((c * 512 + r) << 2)) = kv;
        *(float4*)(sm + (((8 + c) * 512 + r) << 2)) = vv;
    }
    __syncthreads();
    int wid = tid >> 5, lane = tid & 31;
    const float scale = 0.17677669529663689f;  // 1/sqrt(32)
    for (int g = 0; g < 16; g++) {
        int q0 = (g * 8 + wid) * 4;
        float s[4][16];
#pragma unroll
        for (int r = 0; r < 4; r++)
#pragma unroll
            for (int jj = 0; jj < 16; jj++) s[r][jj] = 0.f;
#pragma unroll
        for (int dh = 0; dh < 2; dh++) {
            unsigned long long qp[4][8];
#pragma unroll
            for (int r = 0; r < 4; r++)
#pragma unroll
                for (int c = 0; c < 4; c++) {
                    float4 t = *(const float4*)(base + (size_t)(q0 + r) * QC + dh * 16 + c * 4);
                    qp[r][c * 2 + 0] = pk2(t.x * scale, t.y * scale);
                    qp[r][c * 2 + 1] = pk2(t.z * scale, t.w * scale);
                }
            for (int jj = 0; jj < 16; jj++) {
                int krow = jj * 32 + lane;
                unsigned long long a2[4];
#pragma unroll
                for (int r = 0; r < 4; r++) a2[r] = pk2(0.f, 0.f);
#pragma unroll
                for (int c = 0; c < 4; c++) {
                    ulonglong2 kp = *(const ulonglong2*)(sm + (((dh * 4 + c) * 512 + krow) << 2));
#pragma unroll
                    for (int r = 0; r < 4; r++) {
                        fma2(a2[r], qp[r][c * 2 + 0], kp.x);
                        fma2(a2[r], qp[r][c * 2 + 1], kp.y);
                    }
                }
#pragma unroll
                for (int r = 0; r < 4; r++) {
                    float lo, hi;
                    upk2(a2[r], lo, hi);
                    s[r][jj] += lo + hi;
                }
            }
        }
        float inv[4];
#pragma unroll
        for (int r = 0; r < 4; r++) {
            float mx = -1e30f;
#pragma unroll
            for (int jj = 0; jj < 16; jj++) mx = fmaxf(mx, s[r][jj]);
#pragma unroll
            for (int off = 16; off; off >>= 1) mx = fmaxf(mx, __shfl_xor_sync(0xffffffffu, mx, off));
            float sum = 0.f;
#pragma unroll
            for (int jj = 0; jj < 16; jj++) { s[r][jj] = __expf(s[r][jj] - mx); sum += s[r][jj]; }
#pragma unroll
            for (int off = 16; off; off >>= 1) sum += __shfl_xor_sync(0xffffffffu, sum, off);
            inv[r] = 1.0f / sum;
        }
#pragma unroll
        for (int dh = 0; dh < 2; dh++) {
            unsigned long long o2[4][8];
#pragma unroll
            for (int r = 0; r < 4; r++)
#pragma unroll
                for (int d = 0; d < 8; d++) o2[r][d] = pk2(0.f, 0.f);
            for (int jj = 0; jj < 16; jj++) {
                int vrow = jj * 32 + lane;
                unsigned long long pd[4];
#pragma unroll
                for (int r = 0; r < 4; r++) pd[r] = dup2(s[r][jj]);
#pragma unroll
                for (int c = 0; c < 4; c++) {
                    ulonglong2 vp = *(const ulonglong2*)(sm + (((8 + dh * 4 + c) * 512 + vrow) << 2));
#pragma unroll
                    for (int r = 0; r < 4; r++) {
                        fma2(o2[r][c * 2 + 0], pd[r], vp.x);
                        fma2(o2[r][c * 2 + 1], pd[r], vp.y);
                    }
                }
            }
#pragma unroll
            for (int r = 0; r < 4; r++) {
                float o[16];
#pragma unroll
                for (int d = 0; d < 8; d++) upk2(o2[r][d], o[2 * d], o[2 * d + 1]);
#pragma unroll
                for (int d = 0; d < 16; d++) {
                    float v = o[d];
                    v += __shfl_down_sync(0xffffffffu, v, 16);
                    v += __shfl_down_sync(0xffffffffu, v, 8);
                    v += __shfl_down_sync(0xffffffffu, v, 4);
                    v += __shfl_down_sync(0xffffffffu, v, 2);
                    v += __shfl_down_sync(0xffffffffu, v, 1);
                    o[d] = v;
                }
                if (lane == 0) {
                    float* orow = outp + (size_t)(b * SS + q0 + r) * OC + h * 32 + dh * 16;
                    float iv = inv[r];
#pragma unroll
                    for (int c = 0; c < 4; c++)
                        *(float4*)(orow + c * 4) = make_float4(
                            o[c * 4 + 0] * iv, o[c * 4 + 1] * iv,
                            o[c * 4 + 2] * iv, o[c * 4 + 3] * iv);
                }
            }
        }
    }
}

// ---------------- fused mean over time + final projection ----------------
__global__ void mean_proj_k(const float* __restrict__ attn, const float* __restrict__ W,
                            const float* __restrict__ bias, float* __restrict__ out) {
    __shared__ float sx[OC];
    int b = blockIdx.x, c = threadIdx.x;  // 192 threads
    float s = 0.f;
    for (int t = 0; t < SS; t++) s += attn[(size_t)(b * SS + t) * OC + c];
    sx[c] = s * (1.0f / SS);
    __syncthreads();
    float acc = 0.f;
    const float* wr = W + c * OC;
    for (int k = 0; k < OC; k++) acc += sx[k] * wr[k];
    out[b * OC + c] = acc + bias[c];
}

// ---------------- launch ----------------
extern "C" void kernel_launch(void* const* d_in, const int* in_sizes, int n_in,
                              void* d_out, int out_size) {
    const float* x    = (const float*)d_in[0];
    const int*   ei   = (const int*)d_in[1];
    const float* W0   = (const float*)d_in[3];
    const float* b0   = (const float*)d_in[4];
    const float* W1   = (const float*)d_in[5];
    const float* b1   = (const float*)d_in[6];
    const float* W2   = (const float*)d_in[7];
    const float* b2   = (const float*)d_in[8];
    const float* wih  = (const float*)d_in[9];
    const float* whh  = (const float*)d_in[10];
    const float* bih  = (const float*)d_in[11];
    const float* bhh  = (const float*)d_in[12];
    const float* inW  = (const float*)d_in[13];
    const float* inB  = (const float*)d_in[14];
    const float* outW = (const float*)d_in[15];
    const float* outB = (const float*)d_in[16];
    float* out = (float*)d_out;

    float *xw, *hA, *hB, *xih, *lstm, *qkv, *attn, *dinv, *wihT, *whhT, *inT, *gbias;
    int *deg, *off, *cur;
    int2* elist;
    cudaGetSymbolAddress((void**)&xw, g_xw);
    cudaGetSymbolAddress((void**)&hA, g_hA);
    cudaGetSymbolAddress((void**)&hB, g_hB);
    cudaGetSymbolAddress((void**)&xih, g_xih);
    cudaGetSymbolAddress((void**)&lstm, g_lstm);
    cudaGetSymbolAddress((void**)&qkv, g_qkv);
    cudaGetSymbolAddress((void**)&attn, g_attn);
    cudaGetSymbolAddress((void**)&dinv, g_dinv);
    cudaGetSymbolAddress((void**)&deg, g_deg);
    cudaGetSymbolAddress((void**)&off, g_off);
    cudaGetSymbolAddress((void**)&cur, g_cur);
    cudaGetSymbolAddress((void**)&elist, g_elist);
    cudaGetSymbolAddress((void**)&wihT, g_wihT);
    cudaGetSymbolAddress((void**)&whhT, g_whhT);
    cudaGetSymbolAddress((void**)&inT, g_inT);
    cudaGetSymbolAddress((void**)&gbias, g_gbias);

    cudaFuncSetAttribute(attn_kernel, cudaFuncAttributeMaxDynamicSharedMemorySize, AT_SMEM);

    // prep (layer-1 GEMM at slot 3 so ncu captures it)
    const int PREP_N = 2 * H4 * 192 + QC * 192 + H4;
    prep_k<<<(PREP_N + 255) / 256, 256>>>(wih, whh, inW, bih, bhh, wihT, whhT, inT, gbias);
    zero_i32_k<<<(NN + 255) / 256, 256>>>(deg, NN);
    count_deg_k<<<(NE + 255) / 256, 256>>>(ei, deg);
    sgemm2<false, false><<<dim3(128 / TN, NN / TM), 256>>>(x, W0, nullptr, xw, NN, 128, 128);
    calc_dinv_k<<<(NN + 255) / 256, 256>>>(deg, dinv);
    prefix_k<<<1, 1024>>>(deg, off, cur);
    fill_k<<<(NE + 255) / 256, 256>>>(ei, dinv, cur, elist);

    gather_k<32><<<(NN * 32 + 255) / 256, 256>>>(xw, elist, off, b0, dinv, hA);
    // GCN layer 2
    sgemm2<true, false><<<dim3(128 / TN, NN / TM), 256>>>(hA, W1, nullptr, xw, NN, 128, 128);
    gather_k<32><<<(NN * 32 + 255) / 256, 256>>>(xw, elist, off, b1, dinv, hB);
    // GCN layer 3
    sgemm2<true, false><<<dim3(192 / TN, NN / TM), 256>>>(hB, W2, nullptr, xw, NN, 192, 128);
    gather_k<48><<<(NN * 48 + 255) / 256, 256>>>(xw, elist, off, b2, dinv, hA);

    // LSTM input precompute + recurrence
    sgemm2<true, true><<<dim3(H4 / TN, NN / TM), 256>>>(hA, wihT, gbias, xih, NN, H4, 192);
    lstm_cluster_kernel<<<128, 768>>>(xih, whhT, lstm);
    // QKV projection
    sgemm2<false, true><<<dim3(QC / TN, NN / TM), 256>>>(lstm, inT, inB, qkv, NN, QC, 192);
    // attention
    attn_kernel<<<BB * 6, 256, AT_SMEM>>>(qkv, attn);
    // fused mean + output projection
    mean_proj_k<<<BB, OC>>>(attn, outW, outB, out);
}

// round 16
// speedup vs baseline: 1.8969x; 1.0018x over previous
#include <cuda_runtime.h>
#include <cstdint>
#include <cstddef>

#define NN 32768
#define NE 327680
#define BB 64
#define SS 512
#define OC 192
#define H4 768
#define QC 576

// ---------------- scratch (static device globals; no allocations) ----------------
__device__ float g_xw  [NN * 192];
__device__ float g_hA  [NN * 192];
__device__ float g_hB  [NN * 192];
__device__ float g_xih [(size_t)NN * H4];
__device__ float g_lstm[NN * OC];
__device__ float g_qkv [NN * QC];
__device__ float g_attn[NN * OC];
__device__ float g_dinv[NN];
__device__ int   g_deg [NN];
__device__ int   g_off [NN + 1];
__device__ int   g_cur [NN];
__device__ int2  g_elist[NE];
__device__ float g_wihT[192 * H4];
__device__ float g_whhT[192 * H4];
__device__ float g_inT [192 * QC];
__device__ float g_gbias[H4];

// ---------------- small helpers ----------------
__device__ __forceinline__ unsigned long long pk2(float a, float b) {
    unsigned long long r;
    asm("mov.b64 %0, {%1,%2};" : "=l"(r) : "f"(a), "f"(b));
    return r;
}
__device__ __forceinline__ void upk2(unsigned long long v, float& a, float& b) {
    asm("mov.b64 {%0,%1}, %2;" : "=f"(a), "=f"(b) : "l"(v));
}
__device__ __forceinline__ unsigned long long dup2(float w) {
    unsigned long long r;
    asm volatile("mov.b64 %0, {%1,%1};" : "=l"(r) : "f"(w));
    return r;
}
__device__ __forceinline__ void fma2(unsigned long long& acc, unsigned long long a, unsigned long long b) {
    asm("fma.rn.f32x2 %0, %1, %2, %0;" : "+l"(acc) : "l"(a), "l"(b));
}
__device__ __forceinline__ float sigf(float x) { return 1.0f / (1.0f + __expf(-x)); }
__device__ __forceinline__ uint32_t smem_u32(const void* p) {
    uint32_t a;
    asm("{ .reg .u64 t; cvta.to.shared.u64 t, %1; cvt.u32.u64 %0, t; }" : "=r"(a) : "l"(p));
    return a;
}
#define CLUSTER_SYNC() do { \
    asm volatile("barrier.cluster.arrive.aligned;" ::: "memory"); \
    asm volatile("barrier.cluster.wait.aligned;" ::: "memory"); \
} while (0)

// ---------------- fused prep: 3 transposes + lstm bias ----------------
__global__ void prep_k(const float* __restrict__ wih, const float* __restrict__ whh,
                       const float* __restrict__ inW, const float* __restrict__ bih,
                       const float* __restrict__ bhh,
                       float* __restrict__ wihT, float* __restrict__ whhT,
                       float* __restrict__ inT, float* __restrict__ gbias) {
    int idx = blockIdx.x * blockDim.x + threadIdx.x;
    const int T1 = H4 * 192;
    const int T2 = 2 * T1;
    const int T3 = T2 + QC * 192;
    const int T4 = T3 + H4;
    if (idx < T1) {
        int r = idx / 192, c = idx % 192;
        wihT[c * H4 + r] = wih[idx];
    } else if (idx < T2) {
        int j = idx - T1;
        int r = j / 192, c = j % 192;
        whhT[c * H4 + r] = whh[j];
    } else if (idx < T3) {
        int j = idx - T2;
        int r = j / 192, c = j % 192;
        inT[c * QC + r] = inW[j];
    } else if (idx < T4) {
        int j = idx - T3;
        gbias[j] = bih[j] + bhh[j];
    }
}
__global__ void zero_i32_k(int* p, int n) {
    int i = blockIdx.x * blockDim.x + threadIdx.x;
    if (i < n) p[i] = 0;
}
__global__ void count_deg_k(const int* __restrict__ ei, int* __restrict__ deg) {
    int e = blockIdx.x * blockDim.x + threadIdx.x;
    if (e < NE) atomicAdd(&deg[ei[NE + e]], 1);
}
__global__ void calc_dinv_k(const int* __restrict__ deg, float* __restrict__ dinv) {
    int n = blockIdx.x * blockDim.x + threadIdx.x;
    if (n < NN) dinv[n] = rsqrtf((float)(deg[n] + 1));  // +1 self loop
}
__global__ __launch_bounds__(1024) void prefix_k(const int* __restrict__ deg,
                                                 int* __restrict__ off, int* __restrict__ cur) {
    __shared__ int part[1024];
    int tid = threadIdx.x;
    int base = tid * 32;
    int s = 0;
#pragma unroll
    for (int i = 0; i < 32; i++) s += deg[base + i];
    part[tid] = s;
    __syncthreads();
    for (int d = 1; d < 1024; d <<= 1) {
        int v = (tid >= d) ? part[tid - d] : 0;
        __syncthreads();
        part[tid] += v;
        __syncthreads();
    }
    int pre = (tid > 0) ? part[tid - 1] : 0;
#pragma unroll
    for (int i = 0; i < 32; i++) {
        off[base + i] = pre;
        cur[base + i] = pre;
        pre += deg[base + i];
    }
    if (tid == 1023) off[NN] = pre;
}
__global__ void fill_k(const int* __restrict__ ei, const float* __restrict__ dinv,
                       int* __restrict__ cur, int2* __restrict__ elist) {
    int e = blockIdx.x * blockDim.x + threadIdx.x;
    if (e >= NE) return;
    int s = ei[e], d = ei[NE + e];
    float w = dinv[s] * dinv[d];
    int pos = atomicAdd(&cur[d], 1);
    elist[pos] = make_int2(s, __float_as_int(w));
}

// ---------------- SGEMM 128x64x16 (proven R11) for N % 128 != 0 ----------------
#define TM 128
#define TN 64
#define TK 16
template <bool RELU_A, bool BIAS>
__global__ __launch_bounds__(256, 3) void sgemm2(
    const float* __restrict__ A, const float* __restrict__ Bm,
    const float* __restrict__ bias, float* __restrict__ C,
    int M, int N, int K) {
    __shared__ float As[2][TK][TM + 4];
    __shared__ float Bs[2][TK][TN];
    int tid = threadIdx.x;
    int row0 = blockIdx.y * TM, col0 = blockIdx.x * TN;
    int arow = tid >> 2, acol = (tid & 3) * 4;
    int brow = tid >> 4, bcol = (tid & 15) * 4;
    int tx = tid & 15, ty = tid >> 4;
    const float* Abase = A + (size_t)row0 * K;
    const float* Bbase = Bm + col0;

    {
        float4 a0 = *(const float4*)(Abase + (size_t)arow * K + acol);
        float4 a1 = *(const float4*)(Abase + (size_t)(arow + 64) * K + acol);
        if (RELU_A) {
            a0.x = fmaxf(a0.x, 0.f); a0.y = fmaxf(a0.y, 0.f); a0.z = fmaxf(a0.z, 0.f); a0.w = fmaxf(a0.w, 0.f);
            a1.x = fmaxf(a1.x, 0.f); a1.y = fmaxf(a1.y, 0.f); a1.z = fmaxf(a1.z, 0.f); a1.w = fmaxf(a1.w, 0.f);
        }
        As[0][acol + 0][arow] = a0.x; As[0][acol + 1][arow] = a0.y;
        As[0][acol + 2][arow] = a0.z; As[0][acol + 3][arow] = a0.w;
        As[0][acol + 0][arow + 64] = a1.x; As[0][acol + 1][arow + 64] = a1.y;
        As[0][acol + 2][arow + 64] = a1.z; As[0][acol + 3][arow + 64] = a1.w;
        *(float4*)&Bs[0][brow][bcol] = *(const float4*)(Bbase + (size_t)brow * N + bcol);
    }
    __syncthreads();

    unsigned long long acc2[4][4];
#pragma unroll
    for (int p = 0; p < 4; p++)
#pragma unroll
        for (int j = 0; j < 4; j++) acc2[p][j] = pk2(0.f, 0.f);

    int nc = K / TK;
    float4 pa0, pa1, pb;
    for (int c = 0; c < nc; c++) {
        int s = c & 1;
        if (c + 1 < nc) {
            int k0 = (c + 1) * TK;
            pa0 = *(const float4*)(Abase + (size_t)arow * K + k0 + acol);
            pa1 = *(const float4*)(Abase + (size_t)(arow + 64) * K + k0 + acol);
            pb  = *(const float4*)(Bbase + (size_t)(k0 + brow) * N + bcol);
            if (RELU_A) {
                pa0.x = fmaxf(pa0.x, 0.f); pa0.y = fmaxf(pa0.y, 0.f); pa0.z = fmaxf(pa0.z, 0.f); pa0.w = fmaxf(pa0.w, 0.f);
                pa1.x = fmaxf(pa1.x, 0.f); pa1.y = fmaxf(pa1.y, 0.f); pa1.z = fmaxf(pa1.z, 0.f); pa1.w = fmaxf(pa1.w, 0.f);
            }
        }
#pragma unroll
        for (int k = 0; k < TK; k++) {
            ulonglong2 a0p = *(const ulonglong2*)&As[s][k][ty * 8];
            ulonglong2 a1p = *(const ulonglong2*)&As[s][k][ty * 8 + 4];
            float4 bv = *(const float4*)&Bs[s][k][tx * 4];
            unsigned long long bp0 = dup2(bv.x), bp1 = dup2(bv.y);
            unsigned long long bp2 = dup2(bv.z), bp3 = dup2(bv.w);
            fma2(acc2[0][0], a0p.x, bp0); fma2(acc2[0][1], a0p.x, bp1);
            fma2(acc2[0][2], a0p.x, bp2); fma2(acc2[0][3], a0p.x, bp3);
            fma2(acc2[1][0], a0p.y, bp0); fma2(acc2[1][1], a0p.y, bp1);
            fma2(acc2[1][2], a0p.y, bp2); fma2(acc2[1][3], a0p.y, bp3);
            fma2(acc2[2][0], a1p.x, bp0); fma2(acc2[2][1], a1p.x, bp1);
            fma2(acc2[2][2], a1p.x, bp2); fma2(acc2[2][3], a1p.x, bp3);
            fma2(acc2[3][0], a1p.y, bp0); fma2(acc2[3][1], a1p.y, bp1);
            fma2(acc2[3][2], a1p.y, bp2); fma2(acc2[3][3], a1p.y, bp3);
        }
        if (c + 1 < nc) {
            int d = s ^ 1;
            As[d][acol + 0][arow] = pa0.x; As[d][acol + 1][arow] = pa0.y;
            As[d][acol + 2][arow] = pa0.z; As[d][acol + 3][arow] = pa0.w;
            As[d][acol + 0][arow + 64] = pa1.x; As[d][acol + 1][arow + 64] = pa1.y;
            As[d][acol + 2][arow + 64] = pa1.z; As[d][acol + 3][arow + 64] = pa1.w;
            *(float4*)&Bs[d][brow][bcol] = pb;
        }
        __syncthreads();
    }

    float4 bv = make_float4(0.f, 0.f, 0.f, 0.f);
    if (BIAS) bv = *(const float4*)(bias + col0 + tx * 4);
#pragma unroll
    for (int p = 0; p < 4; p++) {
        float lo[4], hi[4];
#pragma unroll
        for (int j = 0; j < 4; j++) upk2(acc2[p][j], lo[j], hi[j]);
        *(float4*)(C + (size_t)(row0 + ty * 8 + 2 * p) * N + col0 + tx * 4) =
            make_float4(lo[0] + bv.x, lo[1] + bv.y, lo[2] + bv.z, lo[3] + bv.w);
        *(float4*)(C + (size_t)(row0 + ty * 8 + 2 * p + 1) * N + col0 + tx * 4) =
            make_float4(hi[0] + bv.x, hi[1] + bv.y, hi[2] + bv.z, hi[3] + bv.w);
    }
}

// ---------------- SGEMM 128x128x16: 8x8 per thread, fewer LDS wavefronts per MAC ----------------
// Thread (tx,ty) owns rows {ty*4..+4, 64+ty*4..+4} x cols {tx*4..+4, 64+tx*4..+4}.
// All fragment LDS are broadcast (A) or lane-contiguous 256B (B): conflict-free.
template <bool RELU_A, bool BIAS>
__global__ __launch_bounds__(256, 2) void sgemm128(
    const float* __restrict__ A, const float* __restrict__ Bm,
    const float* __restrict__ bias, float* __restrict__ C,
    int M, int N, int K) {
    __shared__ __align__(16) float As[2][TK][128 + 4];
    __shared__ __align__(16) float Bs[2][TK][128 + 4];
    int tid = threadIdx.x;
    int row0 = blockIdx.y * 128, col0 = blockIdx.x * 128;
    int tx = tid & 15, ty = tid >> 4;
    int arow = tid >> 1, acol = (tid & 1) * 8;     // A: 8 consecutive k per thread
    int brow = tid >> 4, bcol = (tid & 15) * 8;    // B: 8 consecutive n per thread
    const float* Abase = A + (size_t)row0 * K;
    const float* Bbase = Bm + col0;

    {
        float4 a0 = *(const float4*)(Abase + (size_t)arow * K + acol);
        float4 a1 = *(const float4*)(Abase + (size_t)arow * K + acol + 4);
        if (RELU_A) {
            a0.x = fmaxf(a0.x, 0.f); a0.y = fmaxf(a0.y, 0.f); a0.z = fmaxf(a0.z, 0.f); a0.w = fmaxf(a0.w, 0.f);
            a1.x = fmaxf(a1.x, 0.f); a1.y = fmaxf(a1.y, 0.f); a1.z = fmaxf(a1.z, 0.f); a1.w = fmaxf(a1.w, 0.f);
        }
        As[0][acol + 0][arow] = a0.x; As[0][acol + 1][arow] = a0.y;
        As[0][acol + 2][arow] = a0.z; As[0][acol + 3][arow] = a0.w;
        As[0][acol + 4][arow] = a1.x; As[0][acol + 5][arow] = a1.y;
        As[0][acol + 6][arow] = a1.z; As[0][acol + 7][arow] = a1.w;
        *(float4*)&Bs[0][brow][bcol]     = *(const float4*)(Bbase + (size_t)brow * N + bcol);
        *(float4*)&Bs[0][brow][bcol + 4] = *(const float4*)(Bbase + (size_t)brow * N + bcol + 4);
    }
    __syncthreads();

    unsigned long long acc2[4][8];
#pragma unroll
    for (int p = 0; p < 4; p++)
#pragma unroll
        for (int j = 0; j < 8; j++) acc2[p][j] = pk2(0.f, 0.f);

    int nc = K / TK;
    float4 pa0, pa1, pb0, pb1;
    for (int c = 0; c < nc; c++) {
        int s = c & 1;
        if (c + 1 < nc) {
            int k0 = (c + 1) * TK;
            pa0 = *(const float4*)(Abase + (size_t)arow * K + k0 + acol);
            pa1 = *(const float4*)(Abase + (size_t)arow * K + k0 + acol + 4);
            pb0 = *(const float4*)(Bbase + (size_t)(k0 + brow) * N + bcol);
            pb1 = *(const float4*)(Bbase + (size_t)(k0 + brow) * N + bcol + 4);
            if (RELU_A) {
                pa0.x = fmaxf(pa0.x, 0.f); pa0.y = fmaxf(pa0.y, 0.f); pa0.z = fmaxf(pa0.z, 0.f); pa0.w = fmaxf(pa0.w, 0.f);
                pa1.x = fmaxf(pa1.x, 0.f); pa1.y = fmaxf(pa1.y, 0.f); pa1.z = fmaxf(pa1.z, 0.f); pa1.w = fmaxf(pa1.w, 0.f);
            }
        }
#pragma unroll
        for (int k = 0; k < TK; k++) {
            ulonglong2 a0p = *(const ulonglong2*)&As[s][k][ty * 4];        // rows (t,t+1),(t+2,t+3)
            ulonglong2 a1p = *(const ulonglong2*)&As[s][k][64 + ty * 4];
            float4 b0 = *(const float4*)&Bs[s][k][tx * 4];
            float4 b1 = *(const float4*)&Bs[s][k][64 + tx * 4];
            unsigned long long ap[4] = {a0p.x, a0p.y, a1p.x, a1p.y};
            unsigned long long bp[8] = {dup2(b0.x), dup2(b0.y), dup2(b0.z), dup2(b0.w),
                                        dup2(b1.x), dup2(b1.y), dup2(b1.z), dup2(b1.w)};
#pragma unroll
            for (int p = 0; p < 4; p++)
#pragma unroll
                for (int j = 0; j < 8; j++)
                    fma2(acc2[p][j], ap[p], bp[j]);
        }
        if (c + 1 < nc) {
            int d = s ^ 1;
            As[d][acol + 0][arow] = pa0.x; As[d][acol + 1][arow] = pa0.y;
            As[d][acol + 2][arow] = pa0.z; As[d][acol + 3][arow] = pa0.w;
            As[d][acol + 4][arow] = pa1.x; As[d][acol + 5][arow] = pa1.y;
            As[d][acol + 6][arow] = pa1.z; As[d][acol + 7][arow] = pa1.w;
            *(float4*)&Bs[d][brow][bcol]     = pb0;
            *(float4*)&Bs[d][brow][bcol + 4] = pb1;
        }
        __syncthreads();
    }

    // epilogue: row pairs p -> base row off {0,2,64,66} + ty*4; col halves j<4 / j>=4
    float4 bv0 = make_float4(0.f, 0.f, 0.f, 0.f), bv1 = bv0;
    if (BIAS) {
        bv0 = *(const float4*)(bias + col0 + tx * 4);
        bv1 = *(const float4*)(bias + col0 + 64 + tx * 4);
    }
    const int rof[4] = {0, 2, 64, 66};
#pragma unroll
    for (int p = 0; p < 4; p++) {
        float lo[8], hi[8];
#pragma unroll
        for (int j = 0; j < 8; j++) upk2(acc2[p][j], lo[j], hi[j]);
        int r = row0 + rof[p] + ty * 4;
        *(float4*)(C + (size_t)r * N + col0 + tx * 4) =
            make_float4(lo[0] + bv0.x, lo[1] + bv0.y, lo[2] + bv0.z, lo[3] + bv0.w);
        *(float4*)(C + (size_t)r * N + col0 + 64 + tx * 4) =
            make_float4(lo[4] + bv1.x, lo[5] + bv1.y, lo[6] + bv1.z, lo[7] + bv1.w);
        *(float4*)(C + (size_t)(r + 1) * N + col0 + tx * 4) =
            make_float4(hi[0] + bv0.x, hi[1] + bv0.y, hi[2] + bv0.z, hi[3] + bv0.w);
        *(float4*)(C + (size_t)(r + 1) * N + col0 + 64 + tx * 4) =
            make_float4(hi[4] + bv1.x, hi[5] + bv1.y, hi[6] + bv1.z, hi[7] + bv1.w);
    }
}

// ---------------- GCN gather (no atomics): out[n] = bias + dinv[n]^2*xw[n] + sum_e w*xw[src] ----------------
template <int C4>
__global__ void gather_k(const float* __restrict__ xw, const int2* __restrict__ elist,
                         const int* __restrict__ off, const float* __restrict__ bias,
                         const float* __restrict__ dinv, float* __restrict__ out) {
    int idx = blockIdx.x * blockDim.x + threadIdx.x;
    if (idx >= NN * C4) return;
    int n = idx / C4, cc = idx % C4;
    const int C = C4 * 4;
    float di = dinv[n];
    float d2 = di * di;
    float4 bv = *(const float4*)(bias + cc * 4);
    float4 sv = *(const float4*)(xw + (size_t)n * C + cc * 4);
    float4 acc = make_float4(bv.x + d2 * sv.x, bv.y + d2 * sv.y,
                             bv.z + d2 * sv.z, bv.w + d2 * sv.w);
    int e0 = off[n], e1 = off[n + 1];
    for (int i = e0; i < e1; i++) {
        int2 e = __ldg(&elist[i]);
        float w = __int_as_float(e.y);
        float4 v = *(const float4*)(xw + (size_t)e.x * C + cc * 4);
        acc.x = fmaf(w, v.x, acc.x);
        acc.y = fmaf(w, v.y, acc.y);
        acc.z = fmaf(w, v.z, acc.z);
        acc.w = fmaf(w, v.w, acc.w);
    }
    *(float4*)(out + (size_t)n * C + cc * 4) = acc;
}

// ---------------- LSTM: cluster-of-4 K-split, reg weights, f32x2-packed recurrence (proven R8/R11) ----------------
__global__ __launch_bounds__(768, 1) __cluster_dims__(4, 1, 1)
void lstm_cluster_kernel(const float* __restrict__ xih, const float* __restrict__ whhT,
                         float* __restrict__ out) {
    __shared__ __align__(16) float2 h01[192];
    __shared__ __align__(16) float2 gb[4 * 192];
    __shared__ float2 xs[2][768];
    float wreg[48];
    int tid = threadIdx.x;
    uint32_t rank;
    asm("mov.u32 %0, %%cluster_ctarank;" : "=r"(rank));
    int b0 = (blockIdx.x >> 2) * 2;

#pragma unroll
    for (int k = 0; k < 48; k++)
        wreg[k] = whhT[(size_t)(rank * 48 + k) * 768 + tid];
    if (tid < 192) h01[tid] = make_float2(0.f, 0.f);

    int gidx = tid / 192, u192 = tid % 192;
    uint32_t ro = (uint32_t)(u192 / 48);
    int slot = gidx * 48 + (u192 % 48);
    uint32_t gb_local = smem_u32(&gb[rank * 192 + slot]);
    uint32_t gb_remote;
    asm("mapa.shared::cluster.u32 %0, %1, %2;" : "=r"(gb_remote) : "r"(gb_local), "r"(ro));

    float2 c01 = make_float2(0.f, 0.f);
    int unit = rank * 48 + tid;
    uint32_t hrem[4];
    if (tid < 48) {
        uint32_t hl = smem_u32(&h01[unit]);
#pragma unroll
        for (uint32_t rr = 0; rr < 4; rr++)
            asm("mapa.shared::cluster.u32 %0, %1, %2;" : "=r"(hrem[rr]) : "r"(hl), "r"(rr));
    }
    const float* x0 = xih + (size_t)b0 * SS * H4;
    const float* x1 = x0 + (size_t)SS * H4;
    float* o0 = out + (size_t)b0 * SS * OC;
    float* o1 = o0 + (size_t)SS * OC;
    const int hb = (int)rank * 48;

    xs[0][tid] = make_float2(x0[tid], x1[tid]);

    CLUSTER_SYNC();
    for (int t = 0; t < SS; t++) {
        unsigned long long acc = pk2(0.f, 0.f);
#pragma unroll
        for (int p = 0; p < 24; p++) {
            ulonglong2 hv = *(const ulonglong2*)&h01[hb + 2 * p];
            fma2(acc, dup2(wreg[2 * p]),     hv.x);
            fma2(acc, dup2(wreg[2 * p + 1]), hv.y);
        }
        asm volatile("st.shared::cluster.b64 [%0], %1;" :: "r"(gb_remote), "l"(acc) : "memory");
        float nx0 = 0.f, nx1 = 0.f;
        bool pf = (t + 1 < SS);
        if (pf) {
            nx0 = x0[(size_t)(t + 1) * H4 + tid];
            nx1 = x1[(size_t)(t + 1) * H4 + tid];
        }
        CLUSTER_SYNC();
        if (pf) xs[(t + 1) & 1][tid] = make_float2(nx0, nx1);
        if (tid < 48) {
            const float2* xrow = xs[t & 1];
            float pre0[4], pre1[4];
#pragma unroll
            for (int g = 0; g < 4; g++) {
                float2 s0 = gb[0 * 192 + g * 48 + tid];
                float2 s1 = gb[1 * 192 + g * 48 + tid];
                float2 s2 = gb[2 * 192 + g * 48 + tid];
                float2 s3 = gb[3 * 192 + g * 48 + tid];
                float2 xg = xrow[g * 192 + unit];
                pre0[g] = s0.x + s1.x + s2.x + s3.x + xg.x;
                pre1[g] = s0.y + s1.y + s2.y + s3.y + xg.y;
            }
            float i0 = sigf(pre0[0]), f0 = sigf(pre0[1]), g0 = tanhf(pre0[2]), oo0 = sigf(pre0[3]);
            float i1 = sigf(pre1[0]), f1 = sigf(pre1[1]), g1 = tanhf(pre1[2]), oo1 = sigf(pre1[3]);
            c01.x = f0 * c01.x + i0 * g0;
            c01.y = f1 * c01.y + i1 * g1;
            float h0v = oo0 * tanhf(c01.x);
            float h1v = oo1 * tanhf(c01.y);
            unsigned long long hp = pk2(h0v, h1v);
#pragma unroll
            for (int rr = 0; rr < 4; rr++)
                asm volatile("st.shared::cluster.b64 [%0], %1;" :: "r"(hrem[rr]), "l"(hp) : "memory");
            o0[(size_t)t * OC + unit] = h0v;
            o1[(size_t)t * OC + unit] = h1v;
        }
        CLUSTER_SYNC();
    }
}

// ---------------- attention: one CTA per (b, head), 4 q-rows per warp, f32x2-packed math ----------------
#define AT_SMEM (16 * 512 * 4 * 4)
__global__ __launch_bounds__(256, 1) void attn_kernel(
    const float* __restrict__ qkv, float* __restrict__ outp) {
    extern __shared__ float sm[];
    int bh = blockIdx.x;
    int b = bh / 6, h = bh % 6;
    int tid = threadIdx.x;
    const float* base = qkv + (size_t)b * SS * QC + h * 32;
    for (int i = tid; i < SS * 8; i += 256) {
        int c = i >> 9, r = i & 511;
        float4 kv = *(const float4*)(base + (size_t)r * QC + 192 + c * 4);
        float4 vv = *(const float4*)(base + (size_t)r * QC + 384 + c * 4);
        *(float4*)(sm + ((c * 512 + r) << 2)) = kv;
        *(float4*)(sm + (((8 + c) * 512 + r) << 2)) = vv;
    }
    __syncthreads();
    int wid = tid >> 5, lane = tid & 31;
    const float scale = 0.17677669529663689f;  // 1/sqrt(32)
    for (int g = 0; g < 16; g++) {
        int q0 = (g * 8 + wid) * 4;
        float s[4][16];
#pragma unroll
        for (int r = 0; r < 4; r++)
#pragma unroll
            for (int jj = 0; jj < 16; jj++) s[r][jj] = 0.f;
#pragma unroll
        for (int dh = 0; dh < 2; dh++) {
            unsigned long long qp[4][8];
#pragma unroll
            for (int r = 0; r < 4; r++)
#pragma unroll
                for (int c = 0; c < 4; c++) {
                    float4 t = *(const float4*)(base + (size_t)(q0 + r) * QC + dh * 16 + c * 4);
                    qp[r][c * 2 + 0] = pk2(t.x * scale, t.y * scale);
                    qp[r][c * 2 + 1] = pk2(t.z * scale, t.w * scale);
                }
            for (int jj = 0; jj < 16; jj++) {
                int krow = jj * 32 + lane;
                unsigned long long a2[4];
#pragma unroll
                for (int r = 0; r < 4; r++) a2[r] = pk2(0.f, 0.f);
#pragma unroll
                for (int c = 0; c < 4; c++) {
                    ulonglong2 kp = *(const ulonglong2*)(sm + (((dh * 4 + c) * 512 + krow) << 2));
#pragma unroll
                    for (int r = 0; r < 4; r++) {
                        fma2(a2[r], qp[r][c * 2 + 0], kp.x);
                        fma2(a2[r], qp[r][c * 2 + 1], kp.y);
                    }
                }
#pragma unroll
                for (int r = 0; r < 4; r++) {
                    float lo, hi;
                    upk2(a2[r], lo, hi);
                    s[r][jj] += lo + hi;
                }
            }
        }
        float inv[4];
#pragma unroll
        for (int r = 0; r < 4; r++) {
            float mx = -1e30f;
#pragma unroll
            for (int jj = 0; jj < 16; jj++) mx = fmaxf(mx, s[r][jj]);
#pragma unroll
            for (int off = 16; off; off >>= 1) mx = fmaxf(mx, __shfl_xor_sync(0xffffffffu, mx, off));
            float sum = 0.f;
#pragma unroll
            for (int jj = 0; jj < 16; jj++) { s[r][jj] = __expf(s[r][jj] - mx); sum += s[r][jj]; }
#pragma unroll
            for (int off = 16; off; off >>= 1) sum += __shfl_xor_sync(0xffffffffu, sum, off);
            inv[r] = 1.0f / sum;
        }
#pragma unroll
        for (int dh = 0; dh < 2; dh++) {
            unsigned long long o2[4][8];
#pragma unroll
            for (int r = 0; r < 4; r++)
#pragma unroll
                for (int d = 0; d < 8; d++) o2[r][d] = pk2(0.f, 0.f);
            for (int jj = 0; jj < 16; jj++) {
                int vrow = jj * 32 + lane;
                unsigned long long pd[4];
#pragma unroll
                for (int r = 0; r < 4; r++) pd[r] = dup2(s[r][jj]);
#pragma unroll
                for (int c = 0; c < 4; c++) {
                    ulonglong2 vp = *(const ulonglong2*)(sm + (((8 + dh * 4 + c) * 512 + vrow) << 2));
#pragma unroll
                    for (int r = 0; r < 4; r++) {
                        fma2(o2[r][c * 2 + 0], pd[r], vp.x);
                        fma2(o2[r][c * 2 + 1], pd[r], vp.y);
                    }
                }
            }
#pragma unroll
            for (int r = 0; r < 4; r++) {
                float o[16];
#pragma unroll
                for (int d = 0; d < 8; d++) upk2(o2[r][d], o[2 * d], o[2 * d + 1]);
#pragma unroll
                for (int d = 0; d < 16; d++) {
                    float v = o[d];
                    v += __shfl_down_sync(0xffffffffu, v, 16);
                    v += __shfl_down_sync(0xffffffffu, v, 8);
                    v += __shfl_down_sync(0xffffffffu, v, 4);
                    v += __shfl_down_sync(0xffffffffu, v, 2);
                    v += __shfl_down_sync(0xffffffffu, v, 1);
                    o[d] = v;
                }
                if (lane == 0) {
                    float* orow = outp + (size_t)(b * SS + q0 + r) * OC + h * 32 + dh * 16;
                    float iv = inv[r];
#pragma unroll
                    for (int c = 0; c < 4; c++)
                        *(float4*)(orow + c * 4) = make_float4(
                            o[c * 4 + 0] * iv, o[c * 4 + 1] * iv,
                            o[c * 4 + 2] * iv, o[c * 4 + 3] * iv);
                }
            }
        }
    }
}

// ---------------- fused mean over time + final projection ----------------
__global__ void mean_proj_k(const float* __restrict__ attn, const float* __restrict__ W,
                            const float* __restrict__ bias, float* __restrict__ out) {
    __shared__ float sx[OC];
    int b = blockIdx.x, c = threadIdx.x;  // 192 threads
    float s = 0.f;
    for (int t = 0; t < SS; t++) s += attn[(size_t)(b * SS + t) * OC + c];
    sx[c] = s * (1.0f / SS);
    __syncthreads();
    float acc = 0.f;
    const float* wr = W + c * OC;
    for (int k = 0; k < OC; k++) acc += sx[k] * wr[k];
    out[b * OC + c] = acc + bias[c];
}

// ---------------- launch ----------------
extern "C" void kernel_launch(void* const* d_in, const int* in_sizes, int n_in,
                              void* d_out, int out_size) {
    const float* x    = (const float*)d_in[0];
    const int*   ei   = (const int*)d_in[1];
    const float* W0   = (const float*)d_in[3];
    const float* b0   = (const float*)d_in[4];
    const float* W1   = (const float*)d_in[5];
    const float* b1   = (const float*)d_in[6];
    const float* W2   = (const float*)d_in[7];
    const float* b2   = (const float*)d_in[8];
    const float* wih  = (const float*)d_in[9];
    const float* whh  = (const float*)d_in[10];
    const float* bih  = (const float*)d_in[11];
    const float* bhh  = (const float*)d_in[12];
    const float* inW  = (const float*)d_in[13];
    const float* inB  = (const float*)d_in[14];
    const float* outW = (const float*)d_in[15];
    const float* outB = (const float*)d_in[16];
    float* out = (float*)d_out;

    float *xw, *hA, *hB, *xih, *lstm, *qkv, *attn, *dinv, *wihT, *whhT, *inT, *gbias;
    int *deg, *off, *cur;
    int2* elist;
    cudaGetSymbolAddress((void**)&xw, g_xw);
    cudaGetSymbolAddress((void**)&hA, g_hA);
    cudaGetSymbolAddress((void**)&hB, g_hB);
    cudaGetSymbolAddress((void**)&xih, g_xih);
    cudaGetSymbolAddress((void**)&lstm, g_lstm);
    cudaGetSymbolAddress((void**)&qkv, g_qkv);
    cudaGetSymbolAddress((void**)&attn, g_attn);
    cudaGetSymbolAddress((void**)&dinv, g_dinv);
    cudaGetSymbolAddress((void**)&deg, g_deg);
    cudaGetSymbolAddress((void**)&off, g_off);
    cudaGetSymbolAddress((void**)&cur, g_cur);
    cudaGetSymbolAddress((void**)&elist, g_elist);
    cudaGetSymbolAddress((void**)&wihT, g_wihT);
    cudaGetSymbolAddress((void**)&whhT, g_whhT);
    cudaGetSymbolAddress((void**)&inT, g_inT);
    cudaGetSymbolAddress((void**)&gbias, g_gbias);

    cudaFuncSetAttribute(attn_kernel, cudaFuncAttributeMaxDynamicSharedMemorySize, AT_SMEM);

    // prep (layer-1 GEMM at slot 3 so ncu captures it — now sgemm128)
    const int PREP_N = 2 * H4 * 192 + QC * 192 + H4;
    prep_k<<<(PREP_N + 255) / 256, 256>>>(wih, whh, inW, bih, bhh, wihT, whhT, inT, gbias);
    zero_i32_k<<<(NN + 255) / 256, 256>>>(deg, NN);
    count_deg_k<<<(NE + 255) / 256, 256>>>(ei, deg);
    sgemm128<false, false><<<dim3(1, NN / 128), 256>>>(x, W0, nullptr, xw, NN, 128, 128);
    calc_dinv_k<<<(NN + 255) / 256, 256>>>(deg, dinv);
    prefix_k<<<1, 1024>>>(deg, off, cur);
    fill_k<<<(NE + 255) / 256, 256>>>(ei, dinv, cur, elist);

    gather_k<32><<<(NN * 32 + 255) / 256, 256>>>(xw, elist, off, b0, dinv, hA);
    // GCN layer 2 (N=128 -> wide kernel)
    sgemm128<true, false><<<dim3(1, NN / 128), 256>>>(hA, W1, nullptr, xw, NN, 128, 128);
    gather_k<32><<<(NN * 32 + 255) / 256, 256>>>(xw, elist, off, b1, dinv, hB);
    // GCN layer 3 (N=192 -> 64-wide kernel)
    sgemm2<true, false><<<dim3(192 / TN, NN / TM), 256>>>(hB, W2, nullptr, xw, NN, 192, 128);
    gather_k<48><<<(NN * 48 + 255) / 256, 256>>>(xw, elist, off, b2, dinv, hA);

    // LSTM input precompute (N=768 -> wide kernel) + recurrence
    sgemm128<true, true><<<dim3(H4 / 128, NN / 128), 256>>>(hA, wihT, gbias, xih, NN, H4, 192);
    lstm_cluster_kernel<<<128, 768>>>(xih, whhT, lstm);
    // QKV projection (N=576 -> 64-wide kernel)
    sgemm2<false, true><<<dim3(QC / TN, NN / TM), 256>>>(lstm, inT, inB, qkv, NN, QC, 192);
    // attention
    attn_kernel<<<BB * 6, 256, AT_SMEM>>>(qkv, attn);
    // fused mean + output projection
    mean_proj_k<<<BB, OC>>>(attn, outW, outB, out);
}